// round 4
// baseline (speedup 1.0000x reference)
#include <cuda_runtime.h>
#include <cstdint>

// Problem constants (fixed shapes)
#define NB 8
#define NH 1024
#define NW 1024
#define NHW (1u << 20)
#define NK 2048
#define MY_NEG_INF (-1e30f)

// ---------------- device scratch (static globals: no allocs allowed) ----------------
__device__ unsigned long long g_cand[NB][NHW];      // packed (value_bits<<32)|~idx
__device__ int                g_cand_cnt[NB];
__device__ unsigned int       g_hist[NB][4096];     // value histogram (mantissa>>11)
__device__ float              g_vals[NB][NK];
__device__ float4             g_boxes[NB][NK];      // x1,y1,x2,y2
__device__ unsigned long long g_supp[NB][NK][32];   // suppression bitmask rows

// ---------------- K0: zero counters/histograms ----------------
__global__ void k_zero() {
    int i = blockIdx.x * blockDim.x + threadIdx.x;
    if (i < NB) g_cand_cnt[i] = 0;
    if (i < NB * 4096) ((unsigned int*)g_hist)[i] = 0u;
}

// ---------------- K1: 3x3 local max + threshold, compact candidates ----------------
// block (32,8), grid (32,128,NB)
__global__ void k_peaks(const float* __restrict__ scores) {
    const int TW = 34, TH = 10;
    __shared__ float tile[TH * TW];
    int bat = blockIdx.z;
    int tx = threadIdx.x, ty = threadIdx.y;
    int tid = ty * 32 + tx;
    int bx0 = blockIdx.x * 32 - 1;
    int by0 = blockIdx.y * 8 - 1;
    const float* sb = scores + (size_t)bat * NHW;

    for (int i = tid; i < TH * TW; i += 256) {
        int r = i / TW, c = i - r * TW;
        int gy = by0 + r, gx = bx0 + c;
        float v = __int_as_float(0xff800000);  // -inf
        if ((unsigned)gy < (unsigned)NH && (unsigned)gx < (unsigned)NW)
            v = sb[gy * NW + gx];
        tile[i] = v;
    }
    __syncthreads();

    int r = ty + 1, c = tx + 1;
    float s = tile[r * TW + c];
    float m = s;
    m = fmaxf(m, tile[(r - 1) * TW + (c - 1)]);
    m = fmaxf(m, tile[(r - 1) * TW + (c    )]);
    m = fmaxf(m, tile[(r - 1) * TW + (c + 1)]);
    m = fmaxf(m, tile[(r    ) * TW + (c - 1)]);
    m = fmaxf(m, tile[(r    ) * TW + (c + 1)]);
    m = fmaxf(m, tile[(r + 1) * TW + (c - 1)]);
    m = fmaxf(m, tile[(r + 1) * TW + (c    )]);
    m = fmaxf(m, tile[(r + 1) * TW + (c + 1)]);

    bool cand = (s > 0.5f) && (s == m);

    int gy = blockIdx.y * 8 + ty;
    int gx = blockIdx.x * 32 + tx;
    unsigned idx = (unsigned)(gy * NW + gx);

    unsigned bal = __ballot_sync(0xFFFFFFFFu, cand);
    if (bal) {
        int lane = tx;
        int rank = __popc(bal & ((1u << lane) - 1u));
        int base = 0;
        if (lane == 0) base = atomicAdd(&g_cand_cnt[bat], __popc(bal));
        base = __shfl_sync(0xFFFFFFFFu, base, 0);
        if (cand) {
            unsigned vb = __float_as_uint(s);  // positive float: bits monotone in value
            g_cand[bat][base + rank] =
                ((unsigned long long)vb << 32) | (unsigned)(~idx);
            // scores in (0.5,1): bits in (0x3F000000,0x3F800000) -> 4096 buckets
            int bkt = (int)(vb >> 11) - 0x7E000;
            bkt = bkt < 0 ? 0 : (bkt > 4095 ? 4095 : bkt);
            atomicAdd(&g_hist[bat][bkt], 1u);
        }
    }
}

// ---------------- K2: threshold + compact + bitonic sort + box decode ----------------
// 1 block (1024 thr) per batch; dynamic smem 8192*8 = 64KB
__global__ void k_select(const float* __restrict__ deltas,
                         const float* __restrict__ sizes,
                         const int* __restrict__ p_stride,
                         const int* __restrict__ p_offy,
                         const int* __restrict__ p_offx) {
    extern __shared__ unsigned long long s_keys[];  // 8192
    __shared__ unsigned int s_thr;
    __shared__ int s_cnt;

    int bat = blockIdx.x;
    int tid = threadIdx.x;

    if (tid == 0) {
        s_cnt = 0;
        unsigned acc = 0;
        int t = 0;
        for (int bkt = 4095; bkt >= 0; --bkt) {
            acc += g_hist[bat][bkt];
            if (acc >= NK) { t = bkt; break; }
        }
        s_thr = ((unsigned)t + 0x7E000u) << 11;
    }
    __syncthreads();
    unsigned thr = s_thr;

    int n = g_cand_cnt[bat];
    for (int i = tid; i < n; i += 1024) {
        unsigned long long key = g_cand[bat][i];
        if ((unsigned)(key >> 32) >= thr) {
            int p = atomicAdd(&s_cnt, 1);
            if (p < 8192) s_keys[p] = key;
        }
    }
    __syncthreads();

    int nsel = s_cnt; if (nsel > 8192) nsel = 8192;
    int nsort = NK;
    while (nsort < nsel) nsort <<= 1;
    for (int i = nsel + tid; i < nsort; i += 1024) s_keys[i] = 0ull;
    __syncthreads();

    // bitonic sort descending (key = value desc, then index asc via ~idx)
    for (int k = 2; k <= nsort; k <<= 1) {
        for (int j = k >> 1; j > 0; j >>= 1) {
            for (int i = tid; i < nsort; i += 1024) {
                int ixj = i ^ j;
                if (ixj > i) {
                    unsigned long long a = s_keys[i];
                    unsigned long long b = s_keys[ixj];
                    bool sw = ((i & k) == 0) ? (a < b) : (a > b);
                    if (sw) { s_keys[i] = b; s_keys[ixj] = a; }
                }
            }
            __syncthreads();
        }
    }

    int stride = p_stride[0];
    int offy   = p_offy[0];
    int offx   = p_offx[0];
    const float* dp = deltas + (size_t)bat * 2 * NHW;
    const float* sp = sizes  + (size_t)bat * 2 * NHW;

    for (int k2 = tid; k2 < NK; k2 += 1024) {
        unsigned long long key = s_keys[k2];
        float v;
        float4 box;
        if (key == 0ull) {
            v = MY_NEG_INF;
            box = make_float4(0.f, 0.f, 0.f, 0.f);
        } else {
            v = __uint_as_float((unsigned)(key >> 32));
            unsigned idx = ~(unsigned)key;
            int ih = (int)(idx >> 10);
            int iw = (int)(idx & 1023u);
            float dx = dp[idx];
            float dy = dp[NHW + idx];
            float sx = sp[idx];
            float sy = sp[NHW + idx];
            float cx = (float)(iw * stride + offx) + dx;
            float cy = (float)(ih * stride + offy) + dy;
            box = make_float4(cx - sx * 0.5f, cy - sy * 0.5f,
                              cx + sx * 0.5f, cy + sy * 0.5f);
        }
        g_vals[bat][k2]  = v;
        g_boxes[bat][k2] = box;
    }
}

// ---------------- K3: suppression bitmask (64x64 tiles, upper triangle) ----------------
// block 64 threads, grid (32, 32, NB)
__global__ void k_iou() {
    int bat = blockIdx.z, rb = blockIdx.y, cb = blockIdx.x;
    int t = threadIdx.x;
    int row = rb * 64 + t;
    if (cb < rb) { g_supp[bat][row][cb] = 0ull; return; }

    __shared__ float4 s_box[64];
    __shared__ float  s_area[64];
    float4 cbx = g_boxes[bat][cb * 64 + t];
    s_box[t] = cbx;
    s_area[t] = (cbx.z - cbx.x) * (cbx.w - cbx.y);
    __syncthreads();

    float4 rbx = g_boxes[bat][row];
    float ra = (rbx.z - rbx.x) * (rbx.w - rbx.y);
    unsigned long long bits = 0ull;
    int jbase = cb * 64;
#pragma unroll 8
    for (int cc = 0; cc < 64; ++cc) {
        float4 o = s_box[cc];
        float ix1 = fmaxf(rbx.x, o.x);
        float iy1 = fmaxf(rbx.y, o.y);
        float ix2 = fminf(rbx.z, o.z);
        float iy2 = fminf(rbx.w, o.w);
        float iw = fmaxf(ix2 - ix1, 0.f);
        float ih = fmaxf(iy2 - iy1, 0.f);
        float inter = iw * ih;
        // iou > 0.5  <=>  inter > 0.5*(ra+oa-inter+eps)   (no division)
        bool sup = inter > 0.5f * (ra + s_area[cc] - inter + 1e-12f);
        if ((jbase + cc) > row && sup) bits |= (1ull << cc);
    }
    g_supp[bat][row][cb] = bits;
}

// ---------------- K4: sequential greedy reduction + outputs ----------------
// 1 block (1024 thr) per batch; warp 0 does the serial reduction
__global__ void k_final(float* __restrict__ out) {
    __shared__ unsigned long long s_valid[32];
    __shared__ unsigned long long s_rem[32];
    int bat = blockIdx.x;
    int tid = threadIdx.x;
    int warp = tid >> 5, lane = tid & 31;

    // build valid bitmap (invalid rows start pre-removed)
    {
        bool v0 = g_vals[bat][warp * 64 + lane]      > MY_NEG_INF;
        bool v1 = g_vals[bat][warp * 64 + 32 + lane] > MY_NEG_INF;
        unsigned b0 = __ballot_sync(0xFFFFFFFFu, v0);
        unsigned b1 = __ballot_sync(0xFFFFFFFFu, v1);
        if (lane == 0) s_valid[warp] = (unsigned long long)b0 | ((unsigned long long)b1 << 32);
    }
    __syncthreads();

    if (warp == 0) {
        unsigned long long rem = ~s_valid[lane];   // lane owns removed-word 'lane'
        const unsigned long long* supp = &g_supp[bat][0][0];
        for (int c = 0; c < 32; ++c) {
            unsigned long long w64 = __shfl_sync(0xFFFFFFFFu, rem, c);
            int ibase = c << 6;
#pragma unroll 8
            for (int bb = 0; bb < 64; ++bb) {
                int i = ibase + bb;
                unsigned long long srow = supp[(size_t)i * 32 + lane];
                unsigned long long sc   = supp[(size_t)i * 32 + c];
                unsigned long long bit  = (w64 >> bb) & 1ull;
                unsigned long long msk  = bit - 1ull;  // alive -> all ones
                rem |= srow & msk;
                w64 |= sc & msk;
            }
        }
        s_rem[lane] = rem;
    }
    __syncthreads();

    // outputs: [scores (B*K)] [bboxes (B*K*4)] [keep (B*K)] as fp32
    const int SC_OFF = 0;
    const int BB_OFF = NB * NK;            // 16384
    const int KP_OFF = NB * NK * 5;        // 81920
    for (int k = tid; k < NK; k += 1024) {
        bool keep = ((s_rem[k >> 6] >> (k & 63)) & 1ull) == 0ull;
        float v = keep ? g_vals[bat][k] : 0.f;
        float4 bx = g_boxes[bat][k];
        if (!keep) bx = make_float4(0.f, 0.f, 0.f, 0.f);
        int gk = bat * NK + k;
        out[SC_OFF + gk] = v;
        float4* ob = (float4*)(out + BB_OFF);
        ob[gk] = bx;
        out[KP_OFF + gk] = keep ? 1.f : 0.f;
    }
}

// ---------------- launch ----------------
extern "C" void kernel_launch(void* const* d_in, const int* in_sizes, int n_in,
                              void* d_out, int out_size) {
    const float* scores = (const float*)d_in[0];
    const float* deltas = (const float*)d_in[1];
    const float* sizes  = (const float*)d_in[2];
    const int* p_stride = (const int*)d_in[3];
    const int* p_offy   = (const int*)d_in[4];
    const int* p_offx   = (const int*)d_in[5];
    float* out = (float*)d_out;

    cudaFuncSetAttribute(k_select, cudaFuncAttributeMaxDynamicSharedMemorySize, 65536);

    k_zero<<<(NB * 4096 + 255) / 256, 256>>>();
    k_peaks<<<dim3(NW / 32, NH / 8, NB), dim3(32, 8, 1)>>>(scores);
    k_select<<<NB, 1024, 65536>>>(deltas, sizes, p_stride, p_offy, p_offx);
    k_iou<<<dim3(NK / 64, NK / 64, NB), 64>>>();
    k_final<<<NB, 1024>>>(out);
}

// round 5
// speedup vs baseline: 2.0805x; 2.0805x over previous
#include <cuda_runtime.h>
#include <cstdint>

// Problem constants (fixed shapes)
#define NB 8
#define NH 1024
#define NW 1024
#define NHW (1u << 20)
#define NK 2048
#define MY_NEG_INF (-1e30f)

// ---------------- device scratch (static globals: no allocs allowed) ----------------
__device__ unsigned long long g_cand[NB][NHW];      // packed (value_bits<<32)|~idx
__device__ int                g_cand_cnt[NB];
__device__ unsigned int       g_hist[NB][4096];     // value histogram (mantissa>>11)
__device__ float              g_vals[NB][NK];
__device__ float4             g_boxes[NB][NK];      // x1,y1,x2,y2
__device__ unsigned long long g_supp[NB][NK][32];   // suppression bitmask rows

// ---------------- K0: zero counters/histograms ----------------
__global__ void k_zero() {
    int i = blockIdx.x * blockDim.x + threadIdx.x;
    if (i < NB) g_cand_cnt[i] = 0;
    if (i < NB * 4096) ((unsigned int*)g_hist)[i] = 0u;
}

// ---------------- K1: 3x3 local max + threshold, compact candidates ----------------
// block (32,8), grid (32,128,NB)
__global__ void k_peaks(const float* __restrict__ scores) {
    const int TW = 34, TH = 10;
    __shared__ float tile[TH * TW];
    int bat = blockIdx.z;
    int tx = threadIdx.x, ty = threadIdx.y;
    int tid = ty * 32 + tx;
    int bx0 = blockIdx.x * 32 - 1;
    int by0 = blockIdx.y * 8 - 1;
    const float* sb = scores + (size_t)bat * NHW;

    for (int i = tid; i < TH * TW; i += 256) {
        int r = i / TW, c = i - r * TW;
        int gy = by0 + r, gx = bx0 + c;
        float v = __int_as_float(0xff800000);  // -inf
        if ((unsigned)gy < (unsigned)NH && (unsigned)gx < (unsigned)NW)
            v = sb[gy * NW + gx];
        tile[i] = v;
    }
    __syncthreads();

    int r = ty + 1, c = tx + 1;
    float s = tile[r * TW + c];
    float m = s;
    m = fmaxf(m, tile[(r - 1) * TW + (c - 1)]);
    m = fmaxf(m, tile[(r - 1) * TW + (c    )]);
    m = fmaxf(m, tile[(r - 1) * TW + (c + 1)]);
    m = fmaxf(m, tile[(r    ) * TW + (c - 1)]);
    m = fmaxf(m, tile[(r    ) * TW + (c + 1)]);
    m = fmaxf(m, tile[(r + 1) * TW + (c - 1)]);
    m = fmaxf(m, tile[(r + 1) * TW + (c    )]);
    m = fmaxf(m, tile[(r + 1) * TW + (c + 1)]);

    bool cand = (s > 0.5f) && (s == m);

    int gy = blockIdx.y * 8 + ty;
    int gx = blockIdx.x * 32 + tx;
    unsigned idx = (unsigned)(gy * NW + gx);

    unsigned bal = __ballot_sync(0xFFFFFFFFu, cand);
    if (bal) {
        int lane = tx;
        int rank = __popc(bal & ((1u << lane) - 1u));
        int base = 0;
        if (lane == 0) base = atomicAdd(&g_cand_cnt[bat], __popc(bal));
        base = __shfl_sync(0xFFFFFFFFu, base, 0);
        if (cand) {
            unsigned vb = __float_as_uint(s);  // positive float: bits monotone in value
            g_cand[bat][base + rank] =
                ((unsigned long long)vb << 32) | (unsigned)(~idx);
            // scores in (0.5,1): bits in (0x3F000000,0x3F800000) -> 4096 buckets
            int bkt = (int)(vb >> 11) - 0x7E000;
            bkt = bkt < 0 ? 0 : (bkt > 4095 ? 4095 : bkt);
            atomicAdd(&g_hist[bat][bkt], 1u);
        }
    }
}

// ---------------- K2: threshold + compact + bitonic sort + box decode ----------------
// 1 block (1024 thr) per batch; dynamic smem 8192*8 = 64KB
__global__ void k_select(const float* __restrict__ deltas,
                         const float* __restrict__ sizes,
                         const int* __restrict__ p_stride,
                         const int* __restrict__ p_offy,
                         const int* __restrict__ p_offx) {
    extern __shared__ unsigned long long s_keys[];  // 8192
    __shared__ unsigned s_gsA[1024];
    __shared__ unsigned s_gsB[1024];
    __shared__ int s_tbkt;
    __shared__ int s_cnt;

    int bat = blockIdx.x;
    int tid = threadIdx.x;

    // ---- parallel threshold: two-level suffix scan over 4096-bin histogram ----
    const unsigned* hh = g_hist[bat];
    unsigned h0 = hh[4 * tid + 0];
    unsigned h1 = hh[4 * tid + 1];
    unsigned h2 = hh[4 * tid + 2];
    unsigned h3 = hh[4 * tid + 3];
    s_gsA[tid] = h0 + h1 + h2 + h3;
    if (tid == 0) { s_tbkt = 0; s_cnt = 0; }
    __syncthreads();

    unsigned* a = s_gsA;
    unsigned* b = s_gsB;
    for (int d = 1; d < 1024; d <<= 1) {
        unsigned v = a[tid];
        if (tid + d < 1024) v += a[tid + d];
        __syncthreads();
        b[tid] = v;
        __syncthreads();
        unsigned* t = a; a = b; b = t;
    }
    // a[g] = inclusive suffix sum of group sums from group g
    {
        unsigned beyond = (tid < 1023) ? a[tid + 1] : 0u;  // groups strictly above
        unsigned S = beyond;
        int loc = -1;
        S += h3; if (S >= NK) loc = 4 * tid + 3;
        if (loc < 0) { S += h2; if (S >= NK) loc = 4 * tid + 2; }
        if (loc < 0) { S += h1; if (S >= NK) loc = 4 * tid + 1; }
        if (loc < 0) { S += h0; if (S >= NK) loc = 4 * tid + 0; }
        if (loc >= 0) atomicMax(&s_tbkt, loc);
    }
    __syncthreads();
    unsigned thr = ((unsigned)s_tbkt + 0x7E000u) << 11;

    // ---- compact survivors into smem ----
    int n = g_cand_cnt[bat];
    for (int i = tid; i < n; i += 1024) {
        unsigned long long key = g_cand[bat][i];
        if ((unsigned)(key >> 32) >= thr) {
            int p = atomicAdd(&s_cnt, 1);
            if (p < 8192) s_keys[p] = key;
        }
    }
    __syncthreads();

    int nsel = s_cnt; if (nsel > 8192) nsel = 8192;
    int nsort = NK;
    while (nsort < nsel) nsort <<= 1;
    for (int i = nsel + tid; i < nsort; i += 1024) s_keys[i] = 0ull;
    __syncthreads();

    // bitonic sort descending (key = value desc, then index asc via ~idx)
    for (int k = 2; k <= nsort; k <<= 1) {
        for (int j = k >> 1; j > 0; j >>= 1) {
            for (int i = tid; i < nsort; i += 1024) {
                int ixj = i ^ j;
                if (ixj > i) {
                    unsigned long long x = s_keys[i];
                    unsigned long long y = s_keys[ixj];
                    bool sw = ((i & k) == 0) ? (x < y) : (x > y);
                    if (sw) { s_keys[i] = y; s_keys[ixj] = x; }
                }
            }
            __syncthreads();
        }
    }

    int stride = p_stride[0];
    int offy   = p_offy[0];
    int offx   = p_offx[0];
    const float* dp = deltas + (size_t)bat * 2 * NHW;
    const float* sp = sizes  + (size_t)bat * 2 * NHW;

    for (int k2 = tid; k2 < NK; k2 += 1024) {
        unsigned long long key = s_keys[k2];
        float v;
        float4 box;
        if (key == 0ull) {
            v = MY_NEG_INF;
            box = make_float4(0.f, 0.f, 0.f, 0.f);
        } else {
            v = __uint_as_float((unsigned)(key >> 32));
            unsigned idx = ~(unsigned)key;
            int ih = (int)(idx >> 10);
            int iw = (int)(idx & 1023u);
            float dx = dp[idx];
            float dy = dp[NHW + idx];
            float sx = sp[idx];
            float sy = sp[NHW + idx];
            float cx = (float)(iw * stride + offx) + dx;
            float cy = (float)(ih * stride + offy) + dy;
            box = make_float4(cx - sx * 0.5f, cy - sy * 0.5f,
                              cx + sx * 0.5f, cy + sy * 0.5f);
        }
        g_vals[bat][k2]  = v;
        g_boxes[bat][k2] = box;
    }
}

// ---------------- K3: suppression bitmask (256 rows x 64 cols per block) ----------------
// block 256 threads, grid (32, 8, NB)
__global__ void k_iou() {
    int bat = blockIdx.z, cb = blockIdx.x;
    int t = threadIdx.x;
    int row = blockIdx.y * 256 + t;
    int jbase = cb * 64;

    __shared__ float4 s_box[64];
    __shared__ float  s_area[64];
    if (t < 64) {
        float4 b = g_boxes[bat][jbase + t];
        s_box[t] = b;
        s_area[t] = (b.z - b.x) * (b.w - b.y);
    }
    __syncthreads();

    unsigned long long bits = 0ull;
    if (jbase + 63 > row) {  // otherwise whole word is at/below diagonal -> 0
        float4 rbx = g_boxes[bat][row];
        float ra = (rbx.z - rbx.x) * (rbx.w - rbx.y);
        unsigned lo = 0u, hi = 0u;
        if (jbase > row) {
            // fully above diagonal: no per-bit position check
#pragma unroll
            for (int cc = 0; cc < 32; ++cc) {
                float4 o = s_box[cc];
                float iw = fminf(rbx.z, o.z) - fmaxf(rbx.x, o.x);
                float ih = fminf(rbx.w, o.w) - fmaxf(rbx.y, o.y);
                float inter = fmaxf(iw, 0.f) * fmaxf(ih, 0.f);
                unsigned sup = inter > 0.5f * (ra + s_area[cc] - inter + 1e-12f);
                lo |= sup << cc;
            }
#pragma unroll
            for (int cc = 32; cc < 64; ++cc) {
                float4 o = s_box[cc];
                float iw = fminf(rbx.z, o.z) - fmaxf(rbx.x, o.x);
                float ih = fminf(rbx.w, o.w) - fmaxf(rbx.y, o.y);
                float inter = fmaxf(iw, 0.f) * fmaxf(ih, 0.f);
                unsigned sup = inter > 0.5f * (ra + s_area[cc] - inter + 1e-12f);
                hi |= sup << (cc - 32);
            }
        } else {
            // diagonal tile: need j > row per bit
#pragma unroll
            for (int cc = 0; cc < 32; ++cc) {
                float4 o = s_box[cc];
                float iw = fminf(rbx.z, o.z) - fmaxf(rbx.x, o.x);
                float ih = fminf(rbx.w, o.w) - fmaxf(rbx.y, o.y);
                float inter = fmaxf(iw, 0.f) * fmaxf(ih, 0.f);
                unsigned sup = (inter > 0.5f * (ra + s_area[cc] - inter + 1e-12f))
                               && (jbase + cc > row);
                lo |= sup << cc;
            }
#pragma unroll
            for (int cc = 32; cc < 64; ++cc) {
                float4 o = s_box[cc];
                float iw = fminf(rbx.z, o.z) - fmaxf(rbx.x, o.x);
                float ih = fminf(rbx.w, o.w) - fmaxf(rbx.y, o.y);
                float inter = fmaxf(iw, 0.f) * fmaxf(ih, 0.f);
                unsigned sup = (inter > 0.5f * (ra + s_area[cc] - inter + 1e-12f))
                               && (jbase + cc > row);
                hi |= sup << (cc - 32);
            }
        }
        bits = (unsigned long long)lo | ((unsigned long long)hi << 32);
    }
    g_supp[bat][row][cb] = bits;
}

// ---------------- K4: greedy reduction with smem double-buffered staging ----------------
// 1 block (1024 thr) per batch; warp 0 does the serial chain, warps 1-31 prefetch
__global__ void k_final(float* __restrict__ out) {
    __shared__ unsigned long long buf[2][2048];   // 2 x 16KB chunk buffers
    __shared__ unsigned long long s_valid[32];
    __shared__ unsigned long long s_rem[32];
    int bat = blockIdx.x;
    int tid = threadIdx.x;
    int warp = tid >> 5, lane = tid & 31;
    const unsigned long long* supp = &g_supp[bat][0][0];

    // valid bitmap (invalid rows start pre-removed)
    {
        bool v0 = g_vals[bat][warp * 64 + lane]      > MY_NEG_INF;
        bool v1 = g_vals[bat][warp * 64 + 32 + lane] > MY_NEG_INF;
        unsigned b0 = __ballot_sync(0xFFFFFFFFu, v0);
        unsigned b1 = __ballot_sync(0xFFFFFFFFu, v1);
        if (lane == 0) s_valid[warp] = (unsigned long long)b0 | ((unsigned long long)b1 << 32);
    }

    // prefetch chunk 0 (rows 0..63 = 2048 words)
    for (int i = tid; i < 2048; i += 1024) buf[0][i] = supp[i];
    __syncthreads();

    unsigned long long rem = 0ull;
    if (warp == 0) rem = ~s_valid[lane];   // lane owns removed-word 'lane'

    for (int c = 0; c < 32; ++c) {
        if (warp == 0) {
            unsigned long long w64 = __shfl_sync(0xFFFFFFFFu, rem, c);
            const unsigned long long* bp = buf[c & 1];
#pragma unroll 8
            for (int bb = 0; bb < 64; ++bb) {
                unsigned long long srow = bp[bb * 32 + lane];
                unsigned long long sc   = bp[bb * 32 + c];      // smem broadcast
                unsigned long long msk  = ((w64 >> bb) & 1ull) - 1ull;  // alive -> all ones
                rem |= srow & msk;
                w64 |= sc & msk;
            }
        } else if (c + 1 < 32) {
            // warps 1..31 prefetch next chunk into the other buffer
            for (int i = tid - 32; i < 2048; i += 992)
                buf[(c + 1) & 1][i] = supp[(size_t)(c + 1) * 2048 + i];
        }
        __syncthreads();
    }
    if (warp == 0) s_rem[lane] = rem;
    __syncthreads();

    // outputs: [scores (B*K)] [bboxes (B*K*4)] [keep (B*K)] as fp32
    const int SC_OFF = 0;
    const int BB_OFF = NB * NK;            // 16384
    const int KP_OFF = NB * NK * 5;        // 81920
    for (int k = tid; k < NK; k += 1024) {
        bool keep = ((s_rem[k >> 6] >> (k & 63)) & 1ull) == 0ull;
        float v = keep ? g_vals[bat][k] : 0.f;
        float4 bx = g_boxes[bat][k];
        if (!keep) bx = make_float4(0.f, 0.f, 0.f, 0.f);
        int gk = bat * NK + k;
        out[SC_OFF + gk] = v;
        float4* ob = (float4*)(out + BB_OFF);
        ob[gk] = bx;
        out[KP_OFF + gk] = keep ? 1.f : 0.f;
    }
}

// ---------------- launch ----------------
extern "C" void kernel_launch(void* const* d_in, const int* in_sizes, int n_in,
                              void* d_out, int out_size) {
    const float* scores = (const float*)d_in[0];
    const float* deltas = (const float*)d_in[1];
    const float* sizes  = (const float*)d_in[2];
    const int* p_stride = (const int*)d_in[3];
    const int* p_offy   = (const int*)d_in[4];
    const int* p_offx   = (const int*)d_in[5];
    float* out = (float*)d_out;

    cudaFuncSetAttribute(k_select, cudaFuncAttributeMaxDynamicSharedMemorySize, 65536);

    k_zero<<<(NB * 4096 + 255) / 256, 256>>>();
    k_peaks<<<dim3(NW / 32, NH / 8, NB), dim3(32, 8, 1)>>>(scores);
    k_select<<<NB, 1024, 65536>>>(deltas, sizes, p_stride, p_offy, p_offx);
    k_iou<<<dim3(NK / 64, NK / 256, NB), 256>>>();
    k_final<<<NB, 1024>>>(out);
}

// round 7
// speedup vs baseline: 2.1926x; 1.0539x over previous
#include <cuda_runtime.h>
#include <cstdint>

// Problem constants (fixed shapes)
#define NB 8
#define NH 1024
#define NW 1024
#define NHW (1u << 20)
#define NK 2048
#define MY_NEG_INF (-1e30f)

// ---------------- device scratch (static globals: no allocs allowed) ----------------
__device__ unsigned long long g_cand[NB][NHW];      // packed (value_bits<<32)|~idx
__device__ int                g_cand_cnt[NB];
__device__ unsigned int       g_hist[NB][4096];     // value histogram
__device__ unsigned int       g_thr[NB];            // per-batch value-bits threshold
__device__ unsigned long long g_sel[NB][8192];      // compacted survivors
__device__ int                g_sel_cnt[NB];
__device__ float              g_vals[NB][NK];
__device__ float4             g_boxes[NB][NK];      // x1,y1,x2,y2
__device__ unsigned long long g_supp[NB][NK][32];   // suppression bitmask rows

// ---------------- K0: zero counters/histograms ----------------
__global__ void k_zero() {
    int i = blockIdx.x * blockDim.x + threadIdx.x;
    if (i < NB) { g_cand_cnt[i] = 0; g_sel_cnt[i] = 0; }
    if (i < NB * 4096) ((unsigned int*)g_hist)[i] = 0u;
}

// ---------------- K1: 3x3 local max + threshold, compact candidates ----------------
// block (32,8), grid (32,128,NB)
__global__ void k_peaks(const float* __restrict__ scores) {
    const int TW = 34, TH = 10;
    __shared__ float tile[TH * TW];
    int bat = blockIdx.z;
    int tx = threadIdx.x, ty = threadIdx.y;
    int tid = ty * 32 + tx;
    int bx0 = blockIdx.x * 32 - 1;
    int by0 = blockIdx.y * 8 - 1;
    const float* sb = scores + (size_t)bat * NHW;

    for (int i = tid; i < TH * TW; i += 256) {
        int r = i / TW, c = i - r * TW;
        int gy = by0 + r, gx = bx0 + c;
        float v = __int_as_float(0xff800000);  // -inf
        if ((unsigned)gy < (unsigned)NH && (unsigned)gx < (unsigned)NW)
            v = sb[gy * NW + gx];
        tile[i] = v;
    }
    __syncthreads();

    int r = ty + 1, c = tx + 1;
    float s = tile[r * TW + c];
    float m = s;
    m = fmaxf(m, tile[(r - 1) * TW + (c - 1)]);
    m = fmaxf(m, tile[(r - 1) * TW + (c    )]);
    m = fmaxf(m, tile[(r - 1) * TW + (c + 1)]);
    m = fmaxf(m, tile[(r    ) * TW + (c - 1)]);
    m = fmaxf(m, tile[(r    ) * TW + (c + 1)]);
    m = fmaxf(m, tile[(r + 1) * TW + (c - 1)]);
    m = fmaxf(m, tile[(r + 1) * TW + (c    )]);
    m = fmaxf(m, tile[(r + 1) * TW + (c + 1)]);

    bool cand = (s > 0.5f) && (s == m);

    int gy = blockIdx.y * 8 + ty;
    int gx = blockIdx.x * 32 + tx;
    unsigned idx = (unsigned)(gy * NW + gx);

    unsigned bal = __ballot_sync(0xFFFFFFFFu, cand);
    if (bal) {
        int lane = tx;
        int rank = __popc(bal & ((1u << lane) - 1u));
        int base = 0;
        if (lane == 0) base = atomicAdd(&g_cand_cnt[bat], __popc(bal));
        base = __shfl_sync(0xFFFFFFFFu, base, 0);
        if (cand) {
            unsigned vb = __float_as_uint(s);  // positive float: bits monotone in value
            g_cand[bat][base + rank] =
                ((unsigned long long)vb << 32) | (unsigned)(~idx);
            // scores in (0.5,1): bits in (0x3F000000,0x3F800000) -> 4096 buckets
            int bkt = (int)(vb >> 11) - 0x7E000;
            bkt = bkt < 0 ? 0 : (bkt > 4095 ? 4095 : bkt);
            atomicAdd(&g_hist[bat][bkt], 1u);
        }
    }
}

// ---------------- K2a: per-batch value threshold from histogram ----------------
// grid NB, block 1024
__global__ void k_thresh() {
    __shared__ unsigned s_gsA[1024];
    __shared__ unsigned s_gsB[1024];
    __shared__ int s_tbkt;
    int bat = blockIdx.x;
    int tid = threadIdx.x;

    const unsigned* hh = g_hist[bat];
    unsigned h0 = hh[4 * tid + 0];
    unsigned h1 = hh[4 * tid + 1];
    unsigned h2 = hh[4 * tid + 2];
    unsigned h3 = hh[4 * tid + 3];
    s_gsA[tid] = h0 + h1 + h2 + h3;
    if (tid == 0) s_tbkt = 0;
    __syncthreads();

    unsigned* a = s_gsA;
    unsigned* b = s_gsB;
    for (int d = 1; d < 1024; d <<= 1) {
        unsigned v = a[tid];
        if (tid + d < 1024) v += a[tid + d];
        __syncthreads();
        b[tid] = v;
        __syncthreads();
        unsigned* t = a; a = b; b = t;
    }
    {
        unsigned beyond = (tid < 1023) ? a[tid + 1] : 0u;  // groups strictly above
        unsigned S = beyond;
        int loc = -1;
        S += h3; if (S >= NK) loc = 4 * tid + 3;
        if (loc < 0) { S += h2; if (S >= NK) loc = 4 * tid + 2; }
        if (loc < 0) { S += h1; if (S >= NK) loc = 4 * tid + 1; }
        if (loc < 0) { S += h0; if (S >= NK) loc = 4 * tid + 0; }
        if (loc >= 0) atomicMax(&s_tbkt, loc);
    }
    __syncthreads();
    if (tid == 0) g_thr[bat] = ((unsigned)s_tbkt + 0x7E000u) << 11;
}

// ---------------- K2b: compact survivors (full-chip) ----------------
// grid (32, NB), block 256
__global__ void k_compact() {
    int bat = blockIdx.y;
    unsigned thr = g_thr[bat];
    int n = g_cand_cnt[bat];
    int step = gridDim.x * 256;
    int lane = threadIdx.x & 31;
    for (int i = blockIdx.x * 256 + threadIdx.x; i < n; i += step) {
        unsigned long long key = g_cand[bat][i];
        bool sel = (unsigned)(key >> 32) >= thr;
        unsigned bal = __ballot_sync(0xFFFFFFFFu, sel);
        if (bal) {
            int rank = __popc(bal & ((1u << lane) - 1u));
            int base = 0;
            if (lane == 0) base = atomicAdd(&g_sel_cnt[bat], __popc(bal));
            base = __shfl_sync(0xFFFFFFFFu, base, 0);
            if (sel && base + rank < 8192) g_sel[bat][base + rank] = key;
        }
    }
}

// ---------------- K2c: bitonic sort + box decode ----------------
// 1 block (1024 thr) per batch; dynamic smem 8192*8 = 64KB
__global__ void k_sort(const float* __restrict__ deltas,
                       const float* __restrict__ sizes,
                       const int* __restrict__ p_stride,
                       const int* __restrict__ p_offy,
                       const int* __restrict__ p_offx) {
    extern __shared__ unsigned long long s_keys[];  // 8192
    int bat = blockIdx.x;
    int tid = threadIdx.x;

    int nsel = g_sel_cnt[bat]; if (nsel > 8192) nsel = 8192;
    for (int i = tid; i < nsel; i += 1024) s_keys[i] = g_sel[bat][i];
    int nsort = NK;
    while (nsort < nsel) nsort <<= 1;
    for (int i = nsel + tid; i < nsort; i += 1024) s_keys[i] = 0ull;
    __syncthreads();

    // bitonic sort descending (key = value desc, then index asc via ~idx)
    int half = nsort >> 1;
    for (int k = 2; k <= nsort; k <<= 1) {
        for (int j = k >> 1; j > 0; j >>= 1) {
            for (int p = tid; p < half; p += 1024) {
                int i = ((p & ~(j - 1)) << 1) | (p & (j - 1));
                int ixj = i | j;
                unsigned long long x = s_keys[i];
                unsigned long long y = s_keys[ixj];
                bool sw = ((i & k) == 0) ? (x < y) : (x > y);
                if (sw) { s_keys[i] = y; s_keys[ixj] = x; }
            }
            __syncthreads();
        }
    }

    int stride = p_stride[0];
    int offy   = p_offy[0];
    int offx   = p_offx[0];
    const float* dp = deltas + (size_t)bat * 2 * NHW;
    const float* sp = sizes  + (size_t)bat * 2 * NHW;

    for (int k2 = tid; k2 < NK; k2 += 1024) {
        unsigned long long key = s_keys[k2];
        float v;
        float4 box;
        if (key == 0ull) {
            v = MY_NEG_INF;
            box = make_float4(0.f, 0.f, 0.f, 0.f);
        } else {
            v = __uint_as_float((unsigned)(key >> 32));
            unsigned idx = ~(unsigned)key;
            int ih = (int)(idx >> 10);
            int iw = (int)(idx & 1023u);
            float dx = dp[idx];
            float dy = dp[NHW + idx];
            float sx = sp[idx];
            float sy = sp[NHW + idx];
            float cx = (float)(iw * stride + offx) + dx;
            float cy = (float)(ih * stride + offy) + dy;
            box = make_float4(cx - sx * 0.5f, cy - sy * 0.5f,
                              cx + sx * 0.5f, cy + sy * 0.5f);
        }
        g_vals[bat][k2]  = v;
        g_boxes[bat][k2] = box;
    }
}

// ---------------- K3: suppression bitmask (256 rows x 64 cols per block) ----------------
// block 256 threads, grid (32, 8, NB)
__global__ void k_iou() {
    int bat = blockIdx.z, cb = blockIdx.x;
    int t = threadIdx.x;
    int row = blockIdx.y * 256 + t;
    int jbase = cb * 64;

    __shared__ float4 s_box[64];
    __shared__ float  s_area[64];
    if (t < 64) {
        float4 b = g_boxes[bat][jbase + t];
        s_box[t] = b;
        s_area[t] = (b.z - b.x) * (b.w - b.y);
    }
    __syncthreads();

    unsigned long long bits = 0ull;
    if (jbase + 63 > row) {  // otherwise whole word is at/below diagonal -> 0
        float4 rbx = g_boxes[bat][row];
        float ra = (rbx.z - rbx.x) * (rbx.w - rbx.y);
        unsigned lo = 0u, hi = 0u;
        if (jbase > row) {
#pragma unroll
            for (int cc = 0; cc < 32; ++cc) {
                float4 o = s_box[cc];
                float iw = fminf(rbx.z, o.z) - fmaxf(rbx.x, o.x);
                float ih = fminf(rbx.w, o.w) - fmaxf(rbx.y, o.y);
                float inter = fmaxf(iw, 0.f) * fmaxf(ih, 0.f);
                unsigned sup = inter > 0.5f * (ra + s_area[cc] - inter + 1e-12f);
                lo |= sup << cc;
            }
#pragma unroll
            for (int cc = 32; cc < 64; ++cc) {
                float4 o = s_box[cc];
                float iw = fminf(rbx.z, o.z) - fmaxf(rbx.x, o.x);
                float ih = fminf(rbx.w, o.w) - fmaxf(rbx.y, o.y);
                float inter = fmaxf(iw, 0.f) * fmaxf(ih, 0.f);
                unsigned sup = inter > 0.5f * (ra + s_area[cc] - inter + 1e-12f);
                hi |= sup << (cc - 32);
            }
        } else {
#pragma unroll
            for (int cc = 0; cc < 32; ++cc) {
                float4 o = s_box[cc];
                float iw = fminf(rbx.z, o.z) - fmaxf(rbx.x, o.x);
                float ih = fminf(rbx.w, o.w) - fmaxf(rbx.y, o.y);
                float inter = fmaxf(iw, 0.f) * fmaxf(ih, 0.f);
                unsigned sup = (inter > 0.5f * (ra + s_area[cc] - inter + 1e-12f))
                               && (jbase + cc > row);
                lo |= sup << cc;
            }
#pragma unroll
            for (int cc = 32; cc < 64; ++cc) {
                float4 o = s_box[cc];
                float iw = fminf(rbx.z, o.z) - fmaxf(rbx.x, o.x);
                float ih = fminf(rbx.w, o.w) - fmaxf(rbx.y, o.y);
                float inter = fmaxf(iw, 0.f) * fmaxf(ih, 0.f);
                unsigned sup = (inter > 0.5f * (ra + s_area[cc] - inter + 1e-12f))
                               && (jbase + cc > row);
                hi |= sup << (cc - 32);
            }
        }
        bits = (unsigned long long)lo | ((unsigned long long)hi << 32);
    }
    g_supp[bat][row][cb] = bits;
}

// ---------------- K4: greedy reduction with smem double-buffered staging ----------------
// 1 block (1024 thr) per batch; warp 0 does the serial chain, warps 1-31 prefetch
__global__ void k_final(float* __restrict__ out) {
    __shared__ unsigned long long buf[2][2048];   // 2 x 16KB chunk buffers
    __shared__ unsigned long long s_valid[32];
    __shared__ unsigned long long s_rem[32];
    int bat = blockIdx.x;
    int tid = threadIdx.x;
    int warp = tid >> 5, lane = tid & 31;
    const unsigned long long* supp = &g_supp[bat][0][0];

    // valid bitmap (invalid rows start pre-removed)
    {
        bool v0 = g_vals[bat][warp * 64 + lane]      > MY_NEG_INF;
        bool v1 = g_vals[bat][warp * 64 + 32 + lane] > MY_NEG_INF;
        unsigned b0 = __ballot_sync(0xFFFFFFFFu, v0);
        unsigned b1 = __ballot_sync(0xFFFFFFFFu, v1);
        if (lane == 0) s_valid[warp] = (unsigned long long)b0 | ((unsigned long long)b1 << 32);
    }

    // prefetch chunk 0 (rows 0..63 = 2048 words)
    for (int i = tid; i < 2048; i += 1024) buf[0][i] = supp[i];
    __syncthreads();

    unsigned long long rem = 0ull;
    if (warp == 0) rem = ~s_valid[lane];   // lane owns removed-word 'lane'

    for (int c = 0; c < 32; ++c) {
        if (warp == 0) {
            unsigned long long w64 = __shfl_sync(0xFFFFFFFFu, rem, c);
            const unsigned long long* bp = buf[c & 1];
#pragma unroll
            for (int bb = 0; bb < 64; ++bb) {
                unsigned long long srow = bp[bb * 32 + lane];
                unsigned long long sc   = bp[bb * 32 + c];      // smem broadcast
                unsigned long long msk  = ((w64 >> bb) & 1ull) - 1ull;  // alive -> all ones
                rem |= srow & msk;
                w64 |= sc & msk;
            }
        } else if (c + 1 < 32) {
            // warps 1..31 prefetch next chunk into the other buffer
            for (int i = tid - 32; i < 2048; i += 992)
                buf[(c + 1) & 1][i] = supp[(size_t)(c + 1) * 2048 + i];
        }
        __syncthreads();
    }
    if (warp == 0) s_rem[lane] = rem;
    __syncthreads();

    // outputs: [scores (B*K)] [bboxes (B*K*4)] [keep (B*K)] as fp32
    const int SC_OFF = 0;
    const int BB_OFF = NB * NK;            // 16384
    const int KP_OFF = NB * NK * 5;        // 81920
    for (int k = tid; k < NK; k += 1024) {
        bool keep = ((s_rem[k >> 6] >> (k & 63)) & 1ull) == 0ull;
        float v = keep ? g_vals[bat][k] : 0.f;
        float4 bx = g_boxes[bat][k];
        if (!keep) bx = make_float4(0.f, 0.f, 0.f, 0.f);
        int gk = bat * NK + k;
        out[SC_OFF + gk] = v;
        float4* ob = (float4*)(out + BB_OFF);
        ob[gk] = bx;
        out[KP_OFF + gk] = keep ? 1.f : 0.f;
    }
}

// ---------------- launch ----------------
extern "C" void kernel_launch(void* const* d_in, const int* in_sizes, int n_in,
                              void* d_out, int out_size) {
    const float* scores = (const float*)d_in[0];
    const float* deltas = (const float*)d_in[1];
    const float* sizes  = (const float*)d_in[2];
    const int* p_stride = (const int*)d_in[3];
    const int* p_offy   = (const int*)d_in[4];
    const int* p_offx   = (const int*)d_in[5];
    float* out = (float*)d_out;

    cudaFuncSetAttribute(k_sort, cudaFuncAttributeMaxDynamicSharedMemorySize, 65536);

    k_zero<<<(NB * 4096 + 255) / 256, 256>>>();
    k_peaks<<<dim3(NW / 32, NH / 8, NB), dim3(32, 8, 1)>>>(scores);
    k_thresh<<<NB, 1024>>>();
    k_compact<<<dim3(32, NB), 256>>>();
    k_sort<<<NB, 1024, 65536>>>(deltas, sizes, p_stride, p_offy, p_offx);
    k_iou<<<dim3(NK / 64, NK / 256, NB), 256>>>();
    k_final<<<NB, 1024>>>(out);
}

// round 9
// speedup vs baseline: 2.7426x; 1.2509x over previous
#include <cuda_runtime.h>
#include <cstdint>

// Problem constants (fixed shapes)
#define NB 8
#define NH 1024
#define NW 1024
#define NHW (1u << 20)
#define NK 2048
#define MY_NEG_INF (-1e30f)

// ---------------- device scratch (static globals: no allocs allowed) ----------------
// NOTE: zero-initialized at module load; kernels restore zeros after consuming,
// so every kernel_launch call (and graph replay) starts from the same state.
__device__ unsigned long long g_cand[NB][NHW];      // packed (value_bits<<32)|~idx
__device__ int                g_cand_cnt[NB];
__device__ unsigned int       g_hist[NB][4096];     // value histogram
__device__ unsigned int       g_thr[NB];            // per-batch value-bits threshold
__device__ unsigned long long g_sel[NB][8192];      // compacted survivors
__device__ int                g_sel_cnt[NB];
__device__ float              g_vals[NB][NK];
__device__ float4             g_boxes[NB][NK];      // x1,y1,x2,y2
__device__ unsigned long long g_supp[NB][NK][32];   // suppression bitmask rows

// ---------------- K1: 3x3 local max + threshold, compact candidates ----------------
// block (32,8) = 256 thr, each thread does 4 px; tile 128x8; grid (8,128,NB)
__global__ void k_peaks(const float* __restrict__ scores) {
    __shared__ float s_t[10][136];   // 10 rows x (128 + 4-left + 4-right halo)
    const float NINF = __int_as_float(0xff800000);

    int bat = blockIdx.z;
    int tx = threadIdx.x, ty = threadIdx.y;
    int tid = ty * 32 + tx;
    const float* sb = scores + (size_t)bat * NHW;

    int bx0 = blockIdx.x * 128 - 4;   // global col of f4 slot 0
    int by0 = blockIdx.y * 8 - 1;     // global row of tile row 0

    // load 10 rows x 34 float4 (aligned; each quad fully in or out of image)
    for (int i = tid; i < 340; i += 256) {
        int r = i / 34, q = i - r * 34;
        int gy = by0 + r;
        int gx = bx0 + q * 4;
        float4 v = make_float4(NINF, NINF, NINF, NINF);
        if ((unsigned)gy < (unsigned)NH && (unsigned)gx < (unsigned)NW)
            v = *(const float4*)(sb + (size_t)gy * NW + gx);
        *(float4*)&s_t[r][q * 4] = v;
    }
    __syncthreads();

    int r = ty + 1;
    int c = 4 + 4 * tx;   // smem col of first output px
    float4 L0 = *(const float4*)&s_t[r - 1][c - 4];
    float4 L1 = *(const float4*)&s_t[r    ][c - 4];
    float4 L2 = *(const float4*)&s_t[r + 1][c - 4];
    float4 M0 = *(const float4*)&s_t[r - 1][c];
    float4 M1 = *(const float4*)&s_t[r    ][c];
    float4 M2 = *(const float4*)&s_t[r + 1][c];
    float4 R0 = *(const float4*)&s_t[r - 1][c + 4];
    float4 R1 = *(const float4*)&s_t[r    ][c + 4];
    float4 R2 = *(const float4*)&s_t[r + 1][c + 4];

    // column max over 3 rows for columns c-1 .. c+4
    float cm[6];
    cm[0] = fmaxf(fmaxf(L0.w, L1.w), L2.w);
    cm[1] = fmaxf(fmaxf(M0.x, M1.x), M2.x);
    cm[2] = fmaxf(fmaxf(M0.y, M1.y), M2.y);
    cm[3] = fmaxf(fmaxf(M0.z, M1.z), M2.z);
    cm[4] = fmaxf(fmaxf(M0.w, M1.w), M2.w);
    cm[5] = fmaxf(fmaxf(R0.x, R1.x), R2.x);

    float sv[4] = {M1.x, M1.y, M1.z, M1.w};
    bool cand[4];
#pragma unroll
    for (int j = 0; j < 4; ++j) {
        float m = fmaxf(fmaxf(cm[j], cm[j + 1]), cm[j + 2]);
        cand[j] = (sv[j] > 0.5f) && (sv[j] == m);
    }

    int gy = blockIdx.y * 8 + ty;
    int gx0 = blockIdx.x * 128 + 4 * tx;

    unsigned bal[4];
    int pc[4];
#pragma unroll
    for (int j = 0; j < 4; ++j) { bal[j] = __ballot_sync(0xFFFFFFFFu, cand[j]); pc[j] = __popc(bal[j]); }
    int tot = pc[0] + pc[1] + pc[2] + pc[3];
    if (tot) {
        int base = 0;
        if (tx == 0) base = atomicAdd(&g_cand_cnt[bat], tot);
        base = __shfl_sync(0xFFFFFFFFu, base, 0);
        unsigned lmask = (1u << tx) - 1u;
        int pre = 0;
#pragma unroll
        for (int j = 0; j < 4; ++j) {
            if (cand[j]) {
                int pos = base + pre + __popc(bal[j] & lmask);
                unsigned idx = (unsigned)(gy * NW + gx0 + j);
                unsigned vb = __float_as_uint(sv[j]);
                g_cand[bat][pos] = ((unsigned long long)vb << 32) | (unsigned)(~idx);
                int bkt = (int)(vb >> 11) - 0x7E000;
                bkt = bkt < 0 ? 0 : (bkt > 4095 ? 4095 : bkt);
                atomicAdd(&g_hist[bat][bkt], 1u);
            }
            pre += pc[j];
        }
    }
}

// ---------------- K2a: per-batch value threshold from histogram ----------------
// grid NB, block 1024
__global__ void k_thresh() {
    __shared__ unsigned s_gsA[1024];
    __shared__ unsigned s_gsB[1024];
    __shared__ int s_tbkt;
    int bat = blockIdx.x;
    int tid = threadIdx.x;

    unsigned* hh = g_hist[bat];
    unsigned h0 = hh[4 * tid + 0];
    unsigned h1 = hh[4 * tid + 1];
    unsigned h2 = hh[4 * tid + 2];
    unsigned h3 = hh[4 * tid + 3];
    // restore zeros for next call/replay (this block owns this batch's bins)
    hh[4 * tid + 0] = 0u; hh[4 * tid + 1] = 0u;
    hh[4 * tid + 2] = 0u; hh[4 * tid + 3] = 0u;
    s_gsA[tid] = h0 + h1 + h2 + h3;
    if (tid == 0) s_tbkt = 0;
    __syncthreads();

    unsigned* a = s_gsA;
    unsigned* b = s_gsB;
    for (int d = 1; d < 1024; d <<= 1) {
        unsigned v = a[tid];
        if (tid + d < 1024) v += a[tid + d];
        __syncthreads();
        b[tid] = v;
        __syncthreads();
        unsigned* t = a; a = b; b = t;
    }
    {
        unsigned beyond = (tid < 1023) ? a[tid + 1] : 0u;  // groups strictly above
        unsigned S = beyond;
        int loc = -1;
        S += h3; if (S >= NK) loc = 4 * tid + 3;
        if (loc < 0) { S += h2; if (S >= NK) loc = 4 * tid + 2; }
        if (loc < 0) { S += h1; if (S >= NK) loc = 4 * tid + 1; }
        if (loc < 0) { S += h0; if (S >= NK) loc = 4 * tid + 0; }
        if (loc >= 0) atomicMax(&s_tbkt, loc);
    }
    __syncthreads();
    if (tid == 0) g_thr[bat] = ((unsigned)s_tbkt + 0x7E000u) << 11;
}

// ---------------- K2b: compact survivors (full-chip, vectorized) ----------------
// grid (64, NB), block 256
__global__ void k_compact() {
    int bat = blockIdx.y;
    unsigned thr = g_thr[bat];
    int n = g_cand_cnt[bat];
    int nv = (n + 1) >> 1;
    int step = gridDim.x * 256;
    int lane = threadIdx.x & 31;
    unsigned lmask = (1u << lane) - 1u;
    for (int i = blockIdx.x * 256 + threadIdx.x; i < nv; i += step) {
        ulonglong2 kk = *((const ulonglong2*)g_cand[bat] + i);
        bool s0 = (unsigned)(kk.x >> 32) >= thr;
        bool s1 = (2 * i + 1 < n) && ((unsigned)(kk.y >> 32) >= thr);
        unsigned b0 = __ballot_sync(0xFFFFFFFFu, s0);
        unsigned b1 = __ballot_sync(0xFFFFFFFFu, s1);
        if (b0 | b1) {
            int t0 = __popc(b0);
            int base = 0;
            if (lane == 0) base = atomicAdd(&g_sel_cnt[bat], t0 + __popc(b1));
            base = __shfl_sync(0xFFFFFFFFu, base, 0);
            if (s0) { int p = base + __popc(b0 & lmask); if (p < 8192) g_sel[bat][p] = kk.x; }
            if (s1) { int p = base + t0 + __popc(b1 & lmask); if (p < 8192) g_sel[bat][p] = kk.y; }
        }
    }
}

// ---------------- K2c: bitonic sort + box decode ----------------
// 1 block (1024 thr) per batch; dynamic smem 8192*8 = 64KB
__global__ void k_sort(const float* __restrict__ deltas,
                       const float* __restrict__ sizes,
                       const int* __restrict__ p_stride,
                       const int* __restrict__ p_offy,
                       const int* __restrict__ p_offx) {
    extern __shared__ unsigned long long s_keys[];  // 8192
    int bat = blockIdx.x;
    int tid = threadIdx.x;

    int nsel = g_sel_cnt[bat]; if (nsel > 8192) nsel = 8192;
    for (int i = tid; i < nsel; i += 1024) s_keys[i] = g_sel[bat][i];
    int nsort = NK;
    while (nsort < nsel) nsort <<= 1;
    for (int i = nsel + tid; i < nsort; i += 1024) s_keys[i] = 0ull;
    __syncthreads();
    // counters consumed -> restore zeros for next call/replay
    if (tid == 0) { g_sel_cnt[bat] = 0; g_cand_cnt[bat] = 0; }

    // bitonic sort descending (key = value desc, then index asc via ~idx)
    int half = nsort >> 1;
    for (int k = 2; k <= nsort; k <<= 1) {
        for (int j = k >> 1; j > 0; j >>= 1) {
            for (int p = tid; p < half; p += 1024) {
                int i = ((p & ~(j - 1)) << 1) | (p & (j - 1));
                int ixj = i | j;
                unsigned long long x = s_keys[i];
                unsigned long long y = s_keys[ixj];
                bool sw = ((i & k) == 0) ? (x < y) : (x > y);
                if (sw) { s_keys[i] = y; s_keys[ixj] = x; }
            }
            __syncthreads();
        }
    }

    int stride = p_stride[0];
    int offy   = p_offy[0];
    int offx   = p_offx[0];
    const float* dp = deltas + (size_t)bat * 2 * NHW;
    const float* sp = sizes  + (size_t)bat * 2 * NHW;

    for (int k2 = tid; k2 < NK; k2 += 1024) {
        unsigned long long key = s_keys[k2];
        float v;
        float4 box;
        if (key == 0ull) {
            v = MY_NEG_INF;
            box = make_float4(0.f, 0.f, 0.f, 0.f);
        } else {
            v = __uint_as_float((unsigned)(key >> 32));
            unsigned idx = ~(unsigned)key;
            int ih = (int)(idx >> 10);
            int iw = (int)(idx & 1023u);
            float dx = dp[idx];
            float dy = dp[NHW + idx];
            float sx = sp[idx];
            float sy = sp[NHW + idx];
            float cx = (float)(iw * stride + offx) + dx;
            float cy = (float)(ih * stride + offy) + dy;
            box = make_float4(cx - sx * 0.5f, cy - sy * 0.5f,
                              cx + sx * 0.5f, cy + sy * 0.5f);
        }
        g_vals[bat][k2]  = v;
        g_boxes[bat][k2] = box;
    }
}

// ---------------- K3: suppression bitmask (256 rows x 64 cols per block) ----------------
// block 256 threads, grid (32, 8, NB)
__global__ void k_iou() {
    int bat = blockIdx.z, cb = blockIdx.x;
    int t = threadIdx.x;
    int row = blockIdx.y * 256 + t;
    int jbase = cb * 64;

    __shared__ float4 s_box[64];
    __shared__ float  s_area[64];
    if (t < 64) {
        float4 b = g_boxes[bat][jbase + t];
        s_box[t] = b;
        s_area[t] = (b.z - b.x) * (b.w - b.y);
    }
    __syncthreads();

    unsigned long long bits = 0ull;
    if (jbase + 63 > row) {  // otherwise whole word is at/below diagonal -> 0
        float4 rbx = g_boxes[bat][row];
        float ra = (rbx.z - rbx.x) * (rbx.w - rbx.y);
        unsigned lo = 0u, hi = 0u;
        if (jbase > row) {
#pragma unroll
            for (int cc = 0; cc < 32; ++cc) {
                float4 o = s_box[cc];
                float iw = fminf(rbx.z, o.z) - fmaxf(rbx.x, o.x);
                float ih = fminf(rbx.w, o.w) - fmaxf(rbx.y, o.y);
                float inter = fmaxf(iw, 0.f) * fmaxf(ih, 0.f);
                unsigned sup = inter > 0.5f * (ra + s_area[cc] - inter + 1e-12f);
                lo |= sup << cc;
            }
#pragma unroll
            for (int cc = 32; cc < 64; ++cc) {
                float4 o = s_box[cc];
                float iw = fminf(rbx.z, o.z) - fmaxf(rbx.x, o.x);
                float ih = fminf(rbx.w, o.w) - fmaxf(rbx.y, o.y);
                float inter = fmaxf(iw, 0.f) * fmaxf(ih, 0.f);
                unsigned sup = inter > 0.5f * (ra + s_area[cc] - inter + 1e-12f);
                hi |= sup << (cc - 32);
            }
        } else {
#pragma unroll
            for (int cc = 0; cc < 32; ++cc) {
                float4 o = s_box[cc];
                float iw = fminf(rbx.z, o.z) - fmaxf(rbx.x, o.x);
                float ih = fminf(rbx.w, o.w) - fmaxf(rbx.y, o.y);
                float inter = fmaxf(iw, 0.f) * fmaxf(ih, 0.f);
                unsigned sup = (inter > 0.5f * (ra + s_area[cc] - inter + 1e-12f))
                               && (jbase + cc > row);
                lo |= sup << cc;
            }
#pragma unroll
            for (int cc = 32; cc < 64; ++cc) {
                float4 o = s_box[cc];
                float iw = fminf(rbx.z, o.z) - fmaxf(rbx.x, o.x);
                float ih = fminf(rbx.w, o.w) - fmaxf(rbx.y, o.y);
                float inter = fmaxf(iw, 0.f) * fmaxf(ih, 0.f);
                unsigned sup = (inter > 0.5f * (ra + s_area[cc] - inter + 1e-12f))
                               && (jbase + cc > row);
                hi |= sup << (cc - 32);
            }
        }
        bits = (unsigned long long)lo | ((unsigned long long)hi << 32);
    }
    g_supp[bat][row][cb] = bits;
}

// ---------------- K4: greedy reduction with smem double-buffered staging ----------------
// 1 block (1024 thr) per batch; warp 0 does the serial chain, warps 1-31 prefetch
__global__ void k_final(float* __restrict__ out) {
    __shared__ unsigned long long buf[2][2048];   // 2 x 16KB chunk buffers
    __shared__ unsigned long long s_valid[32];
    __shared__ unsigned long long s_rem[32];
    int bat = blockIdx.x;
    int tid = threadIdx.x;
    int warp = tid >> 5, lane = tid & 31;
    const unsigned long long* supp = &g_supp[bat][0][0];

    // valid bitmap (invalid rows start pre-removed)
    {
        bool v0 = g_vals[bat][warp * 64 + lane]      > MY_NEG_INF;
        bool v1 = g_vals[bat][warp * 64 + 32 + lane] > MY_NEG_INF;
        unsigned b0 = __ballot_sync(0xFFFFFFFFu, v0);
        unsigned b1 = __ballot_sync(0xFFFFFFFFu, v1);
        if (lane == 0) s_valid[warp] = (unsigned long long)b0 | ((unsigned long long)b1 << 32);
    }

    // prefetch chunk 0 (rows 0..63 = 2048 words)
    for (int i = tid; i < 2048; i += 1024) buf[0][i] = supp[i];
    __syncthreads();

    unsigned long long rem = 0ull;
    if (warp == 0) rem = ~s_valid[lane];   // lane owns removed-word 'lane'

    for (int c = 0; c < 32; ++c) {
        if (warp == 0) {
            unsigned long long w64 = __shfl_sync(0xFFFFFFFFu, rem, c);
            const unsigned long long* bp = buf[c & 1];
#pragma unroll
            for (int bb = 0; bb < 64; ++bb) {
                unsigned long long srow = bp[bb * 32 + lane];
                unsigned long long sc   = bp[bb * 32 + c];      // smem broadcast
                unsigned long long msk  = ((w64 >> bb) & 1ull) - 1ull;  // alive -> all ones
                rem |= srow & msk;
                w64 |= sc & msk;
            }
        } else if (c + 1 < 32) {
            // warps 1..31 prefetch next chunk into the other buffer
            for (int i = tid - 32; i < 2048; i += 992)
                buf[(c + 1) & 1][i] = supp[(size_t)(c + 1) * 2048 + i];
        }
        __syncthreads();
    }
    if (warp == 0) s_rem[lane] = rem;
    __syncthreads();

    // outputs: [scores (B*K)] [bboxes (B*K*4)] [keep (B*K)] as fp32
    const int SC_OFF = 0;
    const int BB_OFF = NB * NK;            // 16384
    const int KP_OFF = NB * NK * 5;        // 81920
    for (int k = tid; k < NK; k += 1024) {
        bool keep = ((s_rem[k >> 6] >> (k & 63)) & 1ull) == 0ull;
        float v = keep ? g_vals[bat][k] : 0.f;
        float4 bx = g_boxes[bat][k];
        if (!keep) bx = make_float4(0.f, 0.f, 0.f, 0.f);
        int gk = bat * NK + k;
        out[SC_OFF + gk] = v;
        float4* ob = (float4*)(out + BB_OFF);
        ob[gk] = bx;
        out[KP_OFF + gk] = keep ? 1.f : 0.f;
    }
}

// ---------------- launch ----------------
extern "C" void kernel_launch(void* const* d_in, const int* in_sizes, int n_in,
                              void* d_out, int out_size) {
    const float* scores = (const float*)d_in[0];
    const float* deltas = (const float*)d_in[1];
    const float* sizes  = (const float*)d_in[2];
    const int* p_stride = (const int*)d_in[3];
    const int* p_offy   = (const int*)d_in[4];
    const int* p_offx   = (const int*)d_in[5];
    float* out = (float*)d_out;

    cudaFuncSetAttribute(k_sort, cudaFuncAttributeMaxDynamicSharedMemorySize, 65536);

    k_peaks<<<dim3(NW / 128, NH / 8, NB), dim3(32, 8, 1)>>>(scores);
    k_thresh<<<NB, 1024>>>();
    k_compact<<<dim3(64, NB), 256>>>();
    k_sort<<<NB, 1024, 65536>>>(deltas, sizes, p_stride, p_offy, p_offx);
    k_iou<<<dim3(NK / 64, NK / 256, NB), 256>>>();
    k_final<<<NB, 1024>>>(out);
}

// round 10
// speedup vs baseline: 4.0959x; 1.4934x over previous
#include <cuda_runtime.h>
#include <cstdint>

// Problem constants (fixed shapes)
#define NB 8
#define NH 1024
#define NW 1024
#define NHW (1u << 20)
#define NK 2048
#define MY_NEG_INF (-1e30f)

typedef unsigned long long ull;

// ---------------- device scratch (static globals: no allocs allowed) ----------------
// NOTE: zero-initialized at module load; kernels restore zeros after consuming,
// so every kernel_launch call (and graph replay) starts from the same state.
__device__ ull          g_cand[NB][NHW];      // packed (value_bits<<32)|~idx
__device__ int          g_cand_cnt[NB];
__device__ unsigned int g_hist[NB][4096];     // value histogram
__device__ unsigned int g_thr[NB];            // per-batch value-bits threshold
__device__ ull          g_sel[NB][8192];      // compacted survivors
__device__ int          g_sel_cnt[NB];
__device__ float        g_vals[NB][NK];
__device__ float4       g_boxes[NB][NK];      // x1,y1,x2,y2
__device__ ull          g_supp[NB][NK][32];   // suppression bitmask rows

// ---------------- K1: 3x3 local max + threshold, compact candidates ----------------
// block (32,8) = 256 thr, each thread does 4 px; tile 128x8; grid (8,128,NB)
__global__ void k_peaks(const float* __restrict__ scores) {
    __shared__ float s_t[10][136];   // 10 rows x (128 + 4-left + 4-right halo)
    const float NINF = __int_as_float(0xff800000);

    int bat = blockIdx.z;
    int tx = threadIdx.x, ty = threadIdx.y;
    int tid = ty * 32 + tx;
    const float* sb = scores + (size_t)bat * NHW;

    int bx0 = blockIdx.x * 128 - 4;   // global col of f4 slot 0
    int by0 = blockIdx.y * 8 - 1;     // global row of tile row 0

    for (int i = tid; i < 340; i += 256) {
        int r = i / 34, q = i - r * 34;
        int gy = by0 + r;
        int gx = bx0 + q * 4;
        float4 v = make_float4(NINF, NINF, NINF, NINF);
        if ((unsigned)gy < (unsigned)NH && (unsigned)gx < (unsigned)NW)
            v = *(const float4*)(sb + (size_t)gy * NW + gx);
        *(float4*)&s_t[r][q * 4] = v;
    }
    __syncthreads();

    int r = ty + 1;
    int c = 4 + 4 * tx;
    float4 L0 = *(const float4*)&s_t[r - 1][c - 4];
    float4 L1 = *(const float4*)&s_t[r    ][c - 4];
    float4 L2 = *(const float4*)&s_t[r + 1][c - 4];
    float4 M0 = *(const float4*)&s_t[r - 1][c];
    float4 M1 = *(const float4*)&s_t[r    ][c];
    float4 M2 = *(const float4*)&s_t[r + 1][c];
    float4 R0 = *(const float4*)&s_t[r - 1][c + 4];
    float4 R1 = *(const float4*)&s_t[r    ][c + 4];
    float4 R2 = *(const float4*)&s_t[r + 1][c + 4];

    float cm[6];
    cm[0] = fmaxf(fmaxf(L0.w, L1.w), L2.w);
    cm[1] = fmaxf(fmaxf(M0.x, M1.x), M2.x);
    cm[2] = fmaxf(fmaxf(M0.y, M1.y), M2.y);
    cm[3] = fmaxf(fmaxf(M0.z, M1.z), M2.z);
    cm[4] = fmaxf(fmaxf(M0.w, M1.w), M2.w);
    cm[5] = fmaxf(fmaxf(R0.x, R1.x), R2.x);

    float sv[4] = {M1.x, M1.y, M1.z, M1.w};
    bool cand[4];
#pragma unroll
    for (int j = 0; j < 4; ++j) {
        float m = fmaxf(fmaxf(cm[j], cm[j + 1]), cm[j + 2]);
        cand[j] = (sv[j] > 0.5f) && (sv[j] == m);
    }

    int gy = blockIdx.y * 8 + ty;
    int gx0 = blockIdx.x * 128 + 4 * tx;

    unsigned bal[4];
    int pc[4];
#pragma unroll
    for (int j = 0; j < 4; ++j) { bal[j] = __ballot_sync(0xFFFFFFFFu, cand[j]); pc[j] = __popc(bal[j]); }
    int tot = pc[0] + pc[1] + pc[2] + pc[3];
    if (tot) {
        int base = 0;
        if (tx == 0) base = atomicAdd(&g_cand_cnt[bat], tot);
        base = __shfl_sync(0xFFFFFFFFu, base, 0);
        unsigned lmask = (1u << tx) - 1u;
        int pre = 0;
#pragma unroll
        for (int j = 0; j < 4; ++j) {
            if (cand[j]) {
                int pos = base + pre + __popc(bal[j] & lmask);
                unsigned idx = (unsigned)(gy * NW + gx0 + j);
                unsigned vb = __float_as_uint(sv[j]);
                g_cand[bat][pos] = ((ull)vb << 32) | (unsigned)(~idx);
                int bkt = (int)(vb >> 11) - 0x7E000;
                bkt = bkt < 0 ? 0 : (bkt > 4095 ? 4095 : bkt);
                atomicAdd(&g_hist[bat][bkt], 1u);
            }
            pre += pc[j];
        }
    }
}

// ---------------- K2a: per-batch value threshold (warp-shuffle two-level scan) ----------------
// grid NB, block 1024
__global__ void k_thresh() {
    __shared__ unsigned s_wtot[32];
    __shared__ unsigned s_wsuf[33];
    __shared__ int s_tbkt;
    int bat = blockIdx.x;
    int tid = threadIdx.x;
    int warp = tid >> 5, lane = tid & 31;

    unsigned* hh = g_hist[bat];
    uint4 h = ((uint4*)hh)[tid];
    ((uint4*)hh)[tid] = make_uint4(0u, 0u, 0u, 0u);   // restore zeros for next replay
    unsigned gsum = h.x + h.y + h.z + h.w;
    if (tid == 0) s_tbkt = 0;

    // warp-level inclusive suffix scan
    unsigned s = gsum;
#pragma unroll
    for (int d = 1; d < 32; d <<= 1) {
        unsigned o = __shfl_down_sync(0xFFFFFFFFu, s, d);
        if (lane + d < 32) s += o;
    }
    if (lane == 0) s_wtot[warp] = s;
    __syncthreads();
    if (warp == 0) {
        unsigned ts = s_wtot[lane];
#pragma unroll
        for (int d = 1; d < 32; d <<= 1) {
            unsigned o = __shfl_down_sync(0xFFFFFFFFu, ts, d);
            if (lane + d < 32) ts += o;
        }
        s_wsuf[lane] = ts;
        if (lane == 0) s_wsuf[32] = 0u;
    }
    __syncthreads();

    unsigned beyond = s_wsuf[warp + 1] + (s - gsum);  // bins strictly above tid's group
    unsigned S = beyond;
    int loc = -1;
    S += h.w; if (S >= NK) loc = 4 * tid + 3;
    if (loc < 0) { S += h.z; if (S >= NK) loc = 4 * tid + 2; }
    if (loc < 0) { S += h.y; if (S >= NK) loc = 4 * tid + 1; }
    if (loc < 0) { S += h.x; if (S >= NK) loc = 4 * tid + 0; }
    if (loc >= 0) atomicMax(&s_tbkt, loc);
    __syncthreads();
    if (tid == 0) g_thr[bat] = ((unsigned)s_tbkt + 0x7E000u) << 11;
}

// ---------------- K2b: compact survivors (full-chip, vectorized) ----------------
// grid (64, NB), block 256
__global__ void k_compact() {
    int bat = blockIdx.y;
    unsigned thr = g_thr[bat];
    int n = g_cand_cnt[bat];
    int nv = (n + 1) >> 1;
    int step = gridDim.x * 256;
    int lane = threadIdx.x & 31;
    unsigned lmask = (1u << lane) - 1u;
    for (int i = blockIdx.x * 256 + threadIdx.x; i < nv; i += step) {
        ulonglong2 kk = *((const ulonglong2*)g_cand[bat] + i);
        bool s0 = (unsigned)(kk.x >> 32) >= thr;
        bool s1 = (2 * i + 1 < n) && ((unsigned)(kk.y >> 32) >= thr);
        unsigned b0 = __ballot_sync(0xFFFFFFFFu, s0);
        unsigned b1 = __ballot_sync(0xFFFFFFFFu, s1);
        if (b0 | b1) {
            int t0 = __popc(b0);
            int base = 0;
            if (lane == 0) base = atomicAdd(&g_sel_cnt[bat], t0 + __popc(b1));
            base = __shfl_sync(0xFFFFFFFFu, base, 0);
            if (s0) { int p = base + __popc(b0 & lmask); if (p < 8192) g_sel[bat][p] = kk.x; }
            if (s1) { int p = base + t0 + __popc(b1 & lmask); if (p < 8192) g_sel[bat][p] = kk.y; }
        }
    }
}

// ---------------- register/shuffle bitonic helpers ----------------
__device__ __forceinline__ void cex(ull& a, ull& b, bool desc) {
    bool sw = desc ? (a < b) : (a > b);
    ull t = sw ? b : a;
    b = sw ? a : b;
    a = t;
}

// phases j = jstart .. 1 of merge step k, elements i0..i0+3 per thread
// (element bits: [1:0]=reg, [6:2]=lane). No barriers.
__device__ __forceinline__ void bitonic_reg(ull v[4], int i0, int k, int jstart) {
    bool desc = ((i0 & k) == 0);
#pragma unroll
    for (int j = 64; j >= 4; j >>= 1) {
        if (j > jstart) continue;
        unsigned lm = (unsigned)j >> 2;
        bool upper = ((i0 & j) == 0);
        bool keepmax = (upper == desc);
#pragma unroll
        for (int r = 0; r < 4; ++r) {
            ull o = __shfl_xor_sync(0xFFFFFFFFu, v[r], lm);
            bool take = keepmax ? (o > v[r]) : (o < v[r]);
            if (take) v[r] = o;
        }
    }
    if (jstart >= 2) {
        cex(v[0], v[2], desc);          // j = 2
        cex(v[1], v[3], desc);
        if (k == 2) {                   // j = 1 (direction flips inside thread only for k==2)
            cex(v[0], v[1], true);
            cex(v[2], v[3], false);
        } else {
            cex(v[0], v[1], desc);
            cex(v[2], v[3], desc);
        }
    } else {                            // jstart == 1 -> k == 2
        cex(v[0], v[1], true);
        cex(v[2], v[3], false);
    }
}

// ---------------- K2c: bitonic sort + box decode ----------------
// 1 block (1024 thr) per batch; dynamic smem 8192*8 = 64KB
__global__ void k_sort(const float* __restrict__ deltas,
                       const float* __restrict__ sizes,
                       const int* __restrict__ p_stride,
                       const int* __restrict__ p_offy,
                       const int* __restrict__ p_offx) {
    extern __shared__ ull s_keys[];  // up to 8192
    int bat = blockIdx.x;
    int tid = threadIdx.x;

    int nsel = g_sel_cnt[bat]; if (nsel > 8192) nsel = 8192;
    for (int i = tid; i < nsel; i += 1024) s_keys[i] = g_sel[bat][i];

    if (nsel <= 4096) {
        // -------- fast path: fixed 4096-element register/shfl bitonic --------
        for (int i = nsel + tid; i < 4096; i += 1024) s_keys[i] = 0ull;
        __syncthreads();
        if (tid == 0) { g_sel_cnt[bat] = 0; g_cand_cnt[bat] = 0; }

        int i0 = tid * 4;
        ull v[4];
#pragma unroll
        for (int r = 0; r < 4; ++r) v[r] = s_keys[i0 + r];

        // k = 2..128: entirely barrier-free
        bitonic_reg(v, i0, 2, 1);
        bitonic_reg(v, i0, 4, 2);
        bitonic_reg(v, i0, 8, 4);
        bitonic_reg(v, i0, 16, 8);
        bitonic_reg(v, i0, 32, 16);
        bitonic_reg(v, i0, 64, 32);
        bitonic_reg(v, i0, 128, 64);
#pragma unroll
        for (int r = 0; r < 4; ++r) s_keys[i0 + r] = v[r];
        __syncthreads();

        // k = 256..4096: smem for j>=128, registers for the j<=64 tail
#pragma unroll 1
        for (int k = 256; k <= 4096; k <<= 1) {
#pragma unroll 1
            for (int j = k >> 1; j >= 128; j >>= 1) {
#pragma unroll
                for (int pp = 0; pp < 2; ++pp) {
                    int p = tid + pp * 1024;
                    int i = ((p & ~(j - 1)) << 1) | (p & (j - 1));
                    int ixj = i | j;
                    ull x = s_keys[i];
                    ull y = s_keys[ixj];
                    bool sw = ((i & k) == 0) ? (x < y) : (x > y);
                    if (sw) { s_keys[i] = y; s_keys[ixj] = x; }
                }
                __syncthreads();
            }
#pragma unroll
            for (int r = 0; r < 4; ++r) v[r] = s_keys[i0 + r];
            bitonic_reg(v, i0, k, 64);
#pragma unroll
            for (int r = 0; r < 4; ++r) s_keys[i0 + r] = v[r];
            __syncthreads();
        }
    } else {
        // -------- fallback: generic smem bitonic, nsort = 8192 --------
        for (int i = nsel + tid; i < 8192; i += 1024) s_keys[i] = 0ull;
        __syncthreads();
        if (tid == 0) { g_sel_cnt[bat] = 0; g_cand_cnt[bat] = 0; }
        const int nsort = 8192;
        int half = nsort >> 1;
        for (int k = 2; k <= nsort; k <<= 1) {
            for (int j = k >> 1; j > 0; j >>= 1) {
                for (int p = tid; p < half; p += 1024) {
                    int i = ((p & ~(j - 1)) << 1) | (p & (j - 1));
                    int ixj = i | j;
                    ull x = s_keys[i];
                    ull y = s_keys[ixj];
                    bool sw = ((i & k) == 0) ? (x < y) : (x > y);
                    if (sw) { s_keys[i] = y; s_keys[ixj] = x; }
                }
                __syncthreads();
            }
        }
    }

    int stride = p_stride[0];
    int offy   = p_offy[0];
    int offx   = p_offx[0];
    const float* dp = deltas + (size_t)bat * 2 * NHW;
    const float* sp = sizes  + (size_t)bat * 2 * NHW;

    for (int k2 = tid; k2 < NK; k2 += 1024) {
        ull key = s_keys[k2];
        float v;
        float4 box;
        if (key == 0ull) {
            v = MY_NEG_INF;
            box = make_float4(0.f, 0.f, 0.f, 0.f);
        } else {
            v = __uint_as_float((unsigned)(key >> 32));
            unsigned idx = ~(unsigned)key;
            int ih = (int)(idx >> 10);
            int iw = (int)(idx & 1023u);
            float dx = dp[idx];
            float dy = dp[NHW + idx];
            float sx = sp[idx];
            float sy = sp[NHW + idx];
            float cx = (float)(iw * stride + offx) + dx;
            float cy = (float)(ih * stride + offy) + dy;
            box = make_float4(cx - sx * 0.5f, cy - sy * 0.5f,
                              cx + sx * 0.5f, cy + sy * 0.5f);
        }
        g_vals[bat][k2]  = v;
        g_boxes[bat][k2] = box;
    }
}

// ---------------- K3: suppression bitmask (256 rows x 64 cols per block) ----------------
// block 256 threads, grid (32, 8, NB)
__global__ void k_iou() {
    int bat = blockIdx.z, cb = blockIdx.x;
    int t = threadIdx.x;
    int row = blockIdx.y * 256 + t;
    int jbase = cb * 64;

    __shared__ float4 s_box[64];
    __shared__ float  s_area[64];
    if (t < 64) {
        float4 b = g_boxes[bat][jbase + t];
        s_box[t] = b;
        s_area[t] = (b.z - b.x) * (b.w - b.y);
    }
    __syncthreads();

    ull bits = 0ull;
    if (jbase + 63 > row) {
        float4 rbx = g_boxes[bat][row];
        float ra = (rbx.z - rbx.x) * (rbx.w - rbx.y);
        unsigned lo = 0u, hi = 0u;
        if (jbase > row) {
#pragma unroll
            for (int cc = 0; cc < 32; ++cc) {
                float4 o = s_box[cc];
                float iw = fminf(rbx.z, o.z) - fmaxf(rbx.x, o.x);
                float ih = fminf(rbx.w, o.w) - fmaxf(rbx.y, o.y);
                float inter = fmaxf(iw, 0.f) * fmaxf(ih, 0.f);
                unsigned sup = inter > 0.5f * (ra + s_area[cc] - inter + 1e-12f);
                lo |= sup << cc;
            }
#pragma unroll
            for (int cc = 32; cc < 64; ++cc) {
                float4 o = s_box[cc];
                float iw = fminf(rbx.z, o.z) - fmaxf(rbx.x, o.x);
                float ih = fminf(rbx.w, o.w) - fmaxf(rbx.y, o.y);
                float inter = fmaxf(iw, 0.f) * fmaxf(ih, 0.f);
                unsigned sup = inter > 0.5f * (ra + s_area[cc] - inter + 1e-12f);
                hi |= sup << (cc - 32);
            }
        } else {
#pragma unroll
            for (int cc = 0; cc < 32; ++cc) {
                float4 o = s_box[cc];
                float iw = fminf(rbx.z, o.z) - fmaxf(rbx.x, o.x);
                float ih = fminf(rbx.w, o.w) - fmaxf(rbx.y, o.y);
                float inter = fmaxf(iw, 0.f) * fmaxf(ih, 0.f);
                unsigned sup = (inter > 0.5f * (ra + s_area[cc] - inter + 1e-12f))
                               && (jbase + cc > row);
                lo |= sup << cc;
            }
#pragma unroll
            for (int cc = 32; cc < 64; ++cc) {
                float4 o = s_box[cc];
                float iw = fminf(rbx.z, o.z) - fmaxf(rbx.x, o.x);
                float ih = fminf(rbx.w, o.w) - fmaxf(rbx.y, o.y);
                float inter = fmaxf(iw, 0.f) * fmaxf(ih, 0.f);
                unsigned sup = (inter > 0.5f * (ra + s_area[cc] - inter + 1e-12f))
                               && (jbase + cc > row);
                hi |= sup << (cc - 32);
            }
        }
        bits = (ull)lo | ((ull)hi << 32);
    }
    g_supp[bat][row][cb] = bits;
}

// ---------------- K4: greedy reduction with smem double-buffered staging ----------------
// 1 block (1024 thr) per batch; warp 0 does the serial chain, warps 1-31 prefetch
__global__ void k_final(float* __restrict__ out) {
    __shared__ ull buf[2][2048];
    __shared__ ull s_valid[32];
    __shared__ ull s_rem[32];
    int bat = blockIdx.x;
    int tid = threadIdx.x;
    int warp = tid >> 5, lane = tid & 31;
    const ull* supp = &g_supp[bat][0][0];

    {
        bool v0 = g_vals[bat][warp * 64 + lane]      > MY_NEG_INF;
        bool v1 = g_vals[bat][warp * 64 + 32 + lane] > MY_NEG_INF;
        unsigned b0 = __ballot_sync(0xFFFFFFFFu, v0);
        unsigned b1 = __ballot_sync(0xFFFFFFFFu, v1);
        if (lane == 0) s_valid[warp] = (ull)b0 | ((ull)b1 << 32);
    }

    for (int i = tid; i < 2048; i += 1024) buf[0][i] = supp[i];
    __syncthreads();

    ull rem = 0ull;
    if (warp == 0) rem = ~s_valid[lane];

    for (int c = 0; c < 32; ++c) {
        if (warp == 0) {
            ull w64 = __shfl_sync(0xFFFFFFFFu, rem, c);
            const ull* bp = buf[c & 1];
#pragma unroll
            for (int bb = 0; bb < 64; ++bb) {
                ull srow = bp[bb * 32 + lane];
                ull sc   = bp[bb * 32 + c];
                ull msk  = ((w64 >> bb) & 1ull) - 1ull;
                rem |= srow & msk;
                w64 |= sc & msk;
            }
        } else if (c + 1 < 32) {
            for (int i = tid - 32; i < 2048; i += 992)
                buf[(c + 1) & 1][i] = supp[(size_t)(c + 1) * 2048 + i];
        }
        __syncthreads();
    }
    if (warp == 0) s_rem[lane] = rem;
    __syncthreads();

    const int SC_OFF = 0;
    const int BB_OFF = NB * NK;
    const int KP_OFF = NB * NK * 5;
    for (int k = tid; k < NK; k += 1024) {
        bool keep = ((s_rem[k >> 6] >> (k & 63)) & 1ull) == 0ull;
        float v = keep ? g_vals[bat][k] : 0.f;
        float4 bx = g_boxes[bat][k];
        if (!keep) bx = make_float4(0.f, 0.f, 0.f, 0.f);
        int gk = bat * NK + k;
        out[SC_OFF + gk] = v;
        float4* ob = (float4*)(out + BB_OFF);
        ob[gk] = bx;
        out[KP_OFF + gk] = keep ? 1.f : 0.f;
    }
}

// ---------------- launch ----------------
extern "C" void kernel_launch(void* const* d_in, const int* in_sizes, int n_in,
                              void* d_out, int out_size) {
    const float* scores = (const float*)d_in[0];
    const float* deltas = (const float*)d_in[1];
    const float* sizes  = (const float*)d_in[2];
    const int* p_stride = (const int*)d_in[3];
    const int* p_offy   = (const int*)d_in[4];
    const int* p_offx   = (const int*)d_in[5];
    float* out = (float*)d_out;

    cudaFuncSetAttribute(k_sort, cudaFuncAttributeMaxDynamicSharedMemorySize, 65536);

    k_peaks<<<dim3(NW / 128, NH / 8, NB), dim3(32, 8, 1)>>>(scores);
    k_thresh<<<NB, 1024>>>();
    k_compact<<<dim3(64, NB), 256>>>();
    k_sort<<<NB, 1024, 65536>>>(deltas, sizes, p_stride, p_offy, p_offx);
    k_iou<<<dim3(NK / 64, NK / 256, NB), 256>>>();
    k_final<<<NB, 1024>>>(out);
}

// round 11
// speedup vs baseline: 4.4884x; 1.0958x over previous
#include <cuda_runtime.h>
#include <cstdint>

// Problem constants (fixed shapes)
#define NB 8
#define NH 1024
#define NW 1024
#define NHW (1u << 20)
#define NK 2048
#define MY_NEG_INF (-1e30f)

typedef unsigned long long ull;

// ---------------- device scratch (static globals: no allocs allowed) ----------------
// NOTE: zero-initialized at module load; kernels restore zeros after consuming,
// so every kernel_launch call (and graph replay) starts from the same state.
__device__ ull          g_cand[NB][NHW];      // packed (value_bits<<32)|~idx
__device__ int          g_cand_cnt[NB];
__device__ unsigned int g_hist[NB][4096];     // value histogram
__device__ unsigned int g_thrA[NB];           // lower bound of buckets > t
__device__ unsigned int g_thrB[NB];           // lower bound of boundary bucket t
__device__ ull          g_selA[NB][2048];     // strictly above boundary bucket
__device__ int          g_selA_cnt[NB];
__device__ ull          g_selB[NB][6144];     // boundary bucket
__device__ int          g_selB_cnt[NB];
__device__ float        g_vals[NB][NK];
__device__ float4       g_boxes[NB][NK];      // x1,y1,x2,y2
__device__ ull          g_supp[NB][NK][32];   // suppression bitmask rows

// ---------------- K1: 3x3 local max + threshold, compact candidates ----------------
// block (32,8) = 256 thr, each thread does 4 px; tile 128x8; grid (8,128,NB)
__global__ void k_peaks(const float* __restrict__ scores) {
    __shared__ float s_t[10][136];   // 10 rows x (128 + 4-left + 4-right halo)
    const float NINF = __int_as_float(0xff800000);

    int bat = blockIdx.z;
    int tx = threadIdx.x, ty = threadIdx.y;
    int tid = ty * 32 + tx;
    const float* sb = scores + (size_t)bat * NHW;

    int bx0 = blockIdx.x * 128 - 4;
    int by0 = blockIdx.y * 8 - 1;

    for (int i = tid; i < 340; i += 256) {
        int r = i / 34, q = i - r * 34;
        int gy = by0 + r;
        int gx = bx0 + q * 4;
        float4 v = make_float4(NINF, NINF, NINF, NINF);
        if ((unsigned)gy < (unsigned)NH && (unsigned)gx < (unsigned)NW)
            v = *(const float4*)(sb + (size_t)gy * NW + gx);
        *(float4*)&s_t[r][q * 4] = v;
    }
    __syncthreads();

    int r = ty + 1;
    int c = 4 + 4 * tx;
    float4 L0 = *(const float4*)&s_t[r - 1][c - 4];
    float4 L1 = *(const float4*)&s_t[r    ][c - 4];
    float4 L2 = *(const float4*)&s_t[r + 1][c - 4];
    float4 M0 = *(const float4*)&s_t[r - 1][c];
    float4 M1 = *(const float4*)&s_t[r    ][c];
    float4 M2 = *(const float4*)&s_t[r + 1][c];
    float4 R0 = *(const float4*)&s_t[r - 1][c + 4];
    float4 R1 = *(const float4*)&s_t[r    ][c + 4];
    float4 R2 = *(const float4*)&s_t[r + 1][c + 4];

    float cm[6];
    cm[0] = fmaxf(fmaxf(L0.w, L1.w), L2.w);
    cm[1] = fmaxf(fmaxf(M0.x, M1.x), M2.x);
    cm[2] = fmaxf(fmaxf(M0.y, M1.y), M2.y);
    cm[3] = fmaxf(fmaxf(M0.z, M1.z), M2.z);
    cm[4] = fmaxf(fmaxf(M0.w, M1.w), M2.w);
    cm[5] = fmaxf(fmaxf(R0.x, R1.x), R2.x);

    float sv[4] = {M1.x, M1.y, M1.z, M1.w};
    bool cand[4];
#pragma unroll
    for (int j = 0; j < 4; ++j) {
        float m = fmaxf(fmaxf(cm[j], cm[j + 1]), cm[j + 2]);
        cand[j] = (sv[j] > 0.5f) && (sv[j] == m);
    }

    int gy = blockIdx.y * 8 + ty;
    int gx0 = blockIdx.x * 128 + 4 * tx;

    unsigned bal[4];
    int pc[4];
#pragma unroll
    for (int j = 0; j < 4; ++j) { bal[j] = __ballot_sync(0xFFFFFFFFu, cand[j]); pc[j] = __popc(bal[j]); }
    int tot = pc[0] + pc[1] + pc[2] + pc[3];
    if (tot) {
        int base = 0;
        if (tx == 0) base = atomicAdd(&g_cand_cnt[bat], tot);
        base = __shfl_sync(0xFFFFFFFFu, base, 0);
        unsigned lmask = (1u << tx) - 1u;
        int pre = 0;
#pragma unroll
        for (int j = 0; j < 4; ++j) {
            if (cand[j]) {
                int pos = base + pre + __popc(bal[j] & lmask);
                unsigned idx = (unsigned)(gy * NW + gx0 + j);
                unsigned vb = __float_as_uint(sv[j]);
                g_cand[bat][pos] = ((ull)vb << 32) | (unsigned)(~idx);
                int bkt = (int)(vb >> 11) - 0x7E000;
                bkt = bkt < 0 ? 0 : (bkt > 4095 ? 4095 : bkt);
                atomicAdd(&g_hist[bat][bkt], 1u);
            }
            pre += pc[j];
        }
    }
}

// ---------------- K2a: per-batch boundary bucket (warp-shuffle two-level scan) ----------------
// grid NB, block 1024
__global__ void k_thresh() {
    __shared__ unsigned s_wtot[32];
    __shared__ unsigned s_wsuf[33];
    __shared__ int s_tbkt;
    int bat = blockIdx.x;
    int tid = threadIdx.x;
    int warp = tid >> 5, lane = tid & 31;

    unsigned* hh = g_hist[bat];
    uint4 h = ((uint4*)hh)[tid];
    ((uint4*)hh)[tid] = make_uint4(0u, 0u, 0u, 0u);   // restore zeros for next replay
    unsigned gsum = h.x + h.y + h.z + h.w;
    if (tid == 0) s_tbkt = 0;

    unsigned s = gsum;
#pragma unroll
    for (int d = 1; d < 32; d <<= 1) {
        unsigned o = __shfl_down_sync(0xFFFFFFFFu, s, d);
        if (lane + d < 32) s += o;
    }
    if (lane == 0) s_wtot[warp] = s;
    __syncthreads();
    if (warp == 0) {
        unsigned ts = s_wtot[lane];
#pragma unroll
        for (int d = 1; d < 32; d <<= 1) {
            unsigned o = __shfl_down_sync(0xFFFFFFFFu, ts, d);
            if (lane + d < 32) ts += o;
        }
        s_wsuf[lane] = ts;
        if (lane == 0) s_wsuf[32] = 0u;
    }
    __syncthreads();

    unsigned beyond = s_wsuf[warp + 1] + (s - gsum);
    unsigned S = beyond;
    int loc = -1;
    S += h.w; if (S >= NK) loc = 4 * tid + 3;
    if (loc < 0) { S += h.z; if (S >= NK) loc = 4 * tid + 2; }
    if (loc < 0) { S += h.y; if (S >= NK) loc = 4 * tid + 1; }
    if (loc < 0) { S += h.x; if (S >= NK) loc = 4 * tid + 0; }
    if (loc >= 0) atomicMax(&s_tbkt, loc);
    __syncthreads();
    if (tid == 0) {
        unsigned t = (unsigned)s_tbkt;
        g_thrB[bat] = (t + 0x7E000u) << 11;
        g_thrA[bat] = (t + 1u + 0x7E000u) << 11;
    }
}

// ---------------- K2b: compact survivors into A (above boundary) and B (boundary) ----------------
// grid (64, NB), block 256
__global__ void k_compact() {
    int bat = blockIdx.y;
    unsigned thrA = g_thrA[bat];
    unsigned thrB = g_thrB[bat];
    int n = g_cand_cnt[bat];
    int nv = (n + 1) >> 1;
    int step = gridDim.x * 256;
    int lane = threadIdx.x & 31;
    unsigned lmask = (1u << lane) - 1u;
    for (int i = blockIdx.x * 256 + threadIdx.x; i < nv; i += step) {
        ulonglong2 kk = *((const ulonglong2*)g_cand[bat] + i);
        unsigned v0 = (unsigned)(kk.x >> 32);
        unsigned v1 = (unsigned)(kk.y >> 32);
        bool in1 = (2 * i + 1 < n);
        bool a0 = v0 >= thrA;
        bool a1 = in1 && (v1 >= thrA);
        bool b0 = !a0 && (v0 >= thrB);
        bool b1 = in1 && !a1 && (v1 >= thrB);

        unsigned bA0 = __ballot_sync(0xFFFFFFFFu, a0);
        unsigned bA1 = __ballot_sync(0xFFFFFFFFu, a1);
        unsigned bB0 = __ballot_sync(0xFFFFFFFFu, b0);
        unsigned bB1 = __ballot_sync(0xFFFFFFFFu, b1);

        if (bA0 | bA1) {
            int t0 = __popc(bA0);
            int base = 0;
            if (lane == 0) base = atomicAdd(&g_selA_cnt[bat], t0 + __popc(bA1));
            base = __shfl_sync(0xFFFFFFFFu, base, 0);
            if (a0) { int p = base + __popc(bA0 & lmask); if (p < 2048) g_selA[bat][p] = kk.x; }
            if (a1) { int p = base + t0 + __popc(bA1 & lmask); if (p < 2048) g_selA[bat][p] = kk.y; }
        }
        if (bB0 | bB1) {
            int t0 = __popc(bB0);
            int base = 0;
            if (lane == 0) base = atomicAdd(&g_selB_cnt[bat], t0 + __popc(bB1));
            base = __shfl_sync(0xFFFFFFFFu, base, 0);
            if (b0) { int p = base + __popc(bB0 & lmask); if (p < 6144) g_selB[bat][p] = kk.x; }
            if (b1) { int p = base + t0 + __popc(bB1 & lmask); if (p < 6144) g_selB[bat][p] = kk.y; }
        }
    }
}

// ---------------- bitonic helpers ----------------
__device__ __forceinline__ void cex(ull& a, ull& b, bool desc) {
    bool sw = desc ? (a < b) : (a > b);
    ull t = sw ? b : a;
    b = sw ? a : b;
    a = t;
}

// ---------------- decode + store one output slot ----------------
__device__ __forceinline__ void decode_store(int bat, int k2, ull key,
                                             const float* dp, const float* sp,
                                             int stride, int offy, int offx) {
    float v;
    float4 box;
    if (key == 0ull) {
        v = MY_NEG_INF;
        box = make_float4(0.f, 0.f, 0.f, 0.f);
    } else {
        v = __uint_as_float((unsigned)(key >> 32));
        unsigned idx = ~(unsigned)key;
        int ih = (int)(idx >> 10);
        int iw = (int)(idx & 1023u);
        float dx = dp[idx];
        float dy = dp[NHW + idx];
        float sx = sp[idx];
        float sy = sp[NHW + idx];
        float cx = (float)(iw * stride + offx) + dx;
        float cy = (float)(ih * stride + offy) + dy;
        box = make_float4(cx - sx * 0.5f, cy - sy * 0.5f,
                          cx + sx * 0.5f, cy + sy * 0.5f);
    }
    g_vals[bat][k2]  = v;
    g_boxes[bat][k2] = box;
}

// ---------------- K2c: sort A (2048 reg bitonic) + B (512 smem bitonic), decode ----------------
// 1 block (1024 thr) per batch; dynamic smem 64KB (fallback needs 8192 keys)
__global__ void k_sort(const float* __restrict__ deltas,
                       const float* __restrict__ sizes,
                       const int* __restrict__ p_stride,
                       const int* __restrict__ p_offy,
                       const int* __restrict__ p_offx) {
    extern __shared__ ull s_keys[];   // fast: [0..512)=B, [512..2560)=A ; fallback: [0..8192)
    int bat = blockIdx.x;
    int tid = threadIdx.x;

    int nA = g_selA_cnt[bat]; if (nA > 2048) nA = 2048;
    int nB = g_selB_cnt[bat]; if (nB > 6144) nB = 6144;
    if (tid == 0) { g_selA_cnt[bat] = 0; g_selB_cnt[bat] = 0; g_cand_cnt[bat] = 0; }

    int stride = p_stride[0];
    int offy   = p_offy[0];
    int offx   = p_offx[0];
    const float* dp = deltas + (size_t)bat * 2 * NHW;
    const float* sp = sizes  + (size_t)bat * 2 * NHW;

    if (nB <= 512) {
        // ---- B: generic 512-element smem bitonic ----
        if (tid < 512) s_keys[tid] = (tid < nB) ? g_selB[bat][tid] : 0ull;
        __syncthreads();
        for (int k = 2; k <= 512; k <<= 1) {
            for (int j = k >> 1; j > 0; j >>= 1) {
                if (tid < 256) {
                    int p = tid;
                    int i = ((p & ~(j - 1)) << 1) | (p & (j - 1));
                    int ixj = i | j;
                    ull x = s_keys[i];
                    ull y = s_keys[ixj];
                    bool sw = ((i & k) == 0) ? (x < y) : (x > y);
                    if (sw) { s_keys[i] = y; s_keys[ixj] = x; }
                }
                __syncthreads();
            }
        }

        // ---- A: 2048-element bitonic, 2 regs/thread ----
        ull* sA = s_keys + 512;
        int i0 = tid * 2;
        ull v0 = (i0     < nA) ? g_selA[bat][i0]     : 0ull;
        ull v1 = (i0 + 1 < nA) ? g_selA[bat][i0 + 1] : 0ull;

        cex(v0, v1, (i0 & 2) == 0);   // k = 2
#pragma unroll
        for (int k = 4; k <= 64; k <<= 1) {   // barrier-free: shfl j=k/2..2, reg j=1
            bool desc = ((i0 & k) == 0);
#pragma unroll
            for (int j = k >> 1; j >= 2; j >>= 1) {
                unsigned lm = (unsigned)j >> 1;
                bool keepmax = (((i0 & j) == 0) == desc);
                ull o0 = __shfl_xor_sync(0xFFFFFFFFu, v0, lm);
                v0 = keepmax ? (o0 > v0 ? o0 : v0) : (o0 < v0 ? o0 : v0);
                ull o1 = __shfl_xor_sync(0xFFFFFFFFu, v1, lm);
                v1 = keepmax ? (o1 > v1 ? o1 : v1) : (o1 < v1 ? o1 : v1);
            }
            cex(v0, v1, desc);
        }
#pragma unroll 1
        for (int k = 128; k <= 2048; k <<= 1) {
            sA[i0] = v0; sA[i0 + 1] = v1;
            __syncthreads();
#pragma unroll 1
            for (int j = k >> 1; j >= 64; j >>= 1) {
                int p = tid;
                int i = ((p & ~(j - 1)) << 1) | (p & (j - 1));
                int ixj = i | j;
                ull x = sA[i];
                ull y = sA[ixj];
                bool sw = ((i & k) == 0) ? (x < y) : (x > y);
                if (sw) { sA[i] = y; sA[ixj] = x; }
                __syncthreads();
            }
            v0 = sA[i0]; v1 = sA[i0 + 1];
            bool desc = ((i0 & k) == 0);
#pragma unroll
            for (int j = 32; j >= 2; j >>= 1) {
                unsigned lm = (unsigned)j >> 1;
                bool keepmax = (((i0 & j) == 0) == desc);
                ull o0 = __shfl_xor_sync(0xFFFFFFFFu, v0, lm);
                v0 = keepmax ? (o0 > v0 ? o0 : v0) : (o0 < v0 ? o0 : v0);
                ull o1 = __shfl_xor_sync(0xFFFFFFFFu, v1, lm);
                v1 = keepmax ? (o1 > v1 ? o1 : v1) : (o1 < v1 ? o1 : v1);
            }
            cex(v0, v1, desc);
        }

        // ---- decode: thread owns output slots i0, i0+1 ----
        // top-2048 = sortedA[0..nA) ++ sortedB[0..2048-nA)
        {
            ull key0 = (i0 < nA) ? v0
                     : ((i0 - nA < nB) ? s_keys[i0 - nA] : 0ull);
            int k1 = i0 + 1;
            ull key1 = (k1 < nA) ? v1
                     : ((k1 - nA < nB) ? s_keys[k1 - nA] : 0ull);
            decode_store(bat, i0, key0, dp, sp, stride, offy, offx);
            decode_store(bat, k1, key1, dp, sp, stride, offy, offx);
        }
    } else {
        // ---- fallback: generic smem bitonic over A ++ B ----
        for (int i = tid; i < nA; i += 1024) s_keys[i] = g_selA[bat][i];
        for (int i = tid; i < nB; i += 1024) s_keys[nA + i] = g_selB[bat][i];
        int nsel = nA + nB;   // <= 8192
        int nsort = NK;
        while (nsort < nsel) nsort <<= 1;
        for (int i = nsel + tid; i < nsort; i += 1024) s_keys[i] = 0ull;
        __syncthreads();
        int half = nsort >> 1;
        for (int k = 2; k <= nsort; k <<= 1) {
            for (int j = k >> 1; j > 0; j >>= 1) {
                for (int p = tid; p < half; p += 1024) {
                    int i = ((p & ~(j - 1)) << 1) | (p & (j - 1));
                    int ixj = i | j;
                    ull x = s_keys[i];
                    ull y = s_keys[ixj];
                    bool sw = ((i & k) == 0) ? (x < y) : (x > y);
                    if (sw) { s_keys[i] = y; s_keys[ixj] = x; }
                }
                __syncthreads();
            }
        }
        for (int k2 = tid; k2 < NK; k2 += 1024)
            decode_store(bat, k2, s_keys[k2], dp, sp, stride, offy, offx);
    }
}

// ---------------- K3: suppression bitmask (256 rows x 64 cols per block) ----------------
// block 256 threads, grid (32, 8, NB)
__global__ void k_iou() {
    int bat = blockIdx.z, cb = blockIdx.x;
    int t = threadIdx.x;
    int row = blockIdx.y * 256 + t;
    int jbase = cb * 64;

    __shared__ float4 s_box[64];
    __shared__ float  s_area[64];
    if (t < 64) {
        float4 b = g_boxes[bat][jbase + t];
        s_box[t] = b;
        s_area[t] = (b.z - b.x) * (b.w - b.y);
    }
    __syncthreads();

    ull bits = 0ull;
    if (jbase + 63 > row) {
        float4 rbx = g_boxes[bat][row];
        float ra = (rbx.z - rbx.x) * (rbx.w - rbx.y);
        unsigned lo = 0u, hi = 0u;
        if (jbase > row) {
#pragma unroll
            for (int cc = 0; cc < 32; ++cc) {
                float4 o = s_box[cc];
                float iw = fminf(rbx.z, o.z) - fmaxf(rbx.x, o.x);
                float ih = fminf(rbx.w, o.w) - fmaxf(rbx.y, o.y);
                float inter = fmaxf(iw, 0.f) * fmaxf(ih, 0.f);
                unsigned sup = inter > 0.5f * (ra + s_area[cc] - inter + 1e-12f);
                lo |= sup << cc;
            }
#pragma unroll
            for (int cc = 32; cc < 64; ++cc) {
                float4 o = s_box[cc];
                float iw = fminf(rbx.z, o.z) - fmaxf(rbx.x, o.x);
                float ih = fminf(rbx.w, o.w) - fmaxf(rbx.y, o.y);
                float inter = fmaxf(iw, 0.f) * fmaxf(ih, 0.f);
                unsigned sup = inter > 0.5f * (ra + s_area[cc] - inter + 1e-12f);
                hi |= sup << (cc - 32);
            }
        } else {
#pragma unroll
            for (int cc = 0; cc < 32; ++cc) {
                float4 o = s_box[cc];
                float iw = fminf(rbx.z, o.z) - fmaxf(rbx.x, o.x);
                float ih = fminf(rbx.w, o.w) - fmaxf(rbx.y, o.y);
                float inter = fmaxf(iw, 0.f) * fmaxf(ih, 0.f);
                unsigned sup = (inter > 0.5f * (ra + s_area[cc] - inter + 1e-12f))
                               && (jbase + cc > row);
                lo |= sup << cc;
            }
#pragma unroll
            for (int cc = 32; cc < 64; ++cc) {
                float4 o = s_box[cc];
                float iw = fminf(rbx.z, o.z) - fmaxf(rbx.x, o.x);
                float ih = fminf(rbx.w, o.w) - fmaxf(rbx.y, o.y);
                float inter = fmaxf(iw, 0.f) * fmaxf(ih, 0.f);
                unsigned sup = (inter > 0.5f * (ra + s_area[cc] - inter + 1e-12f))
                               && (jbase + cc > row);
                hi |= sup << (cc - 32);
            }
        }
        bits = (ull)lo | ((ull)hi << 32);
    }
    g_supp[bat][row][cb] = bits;
}

// ---------------- K4: greedy reduction with smem double-buffered staging ----------------
// 1 block (1024 thr) per batch; warp 0 does the serial chain, warps 1-31 prefetch
__global__ void k_final(float* __restrict__ out) {
    __shared__ ull buf[2][2048];
    __shared__ ull s_valid[32];
    __shared__ ull s_rem[32];
    int bat = blockIdx.x;
    int tid = threadIdx.x;
    int warp = tid >> 5, lane = tid & 31;
    const ull* supp = &g_supp[bat][0][0];

    {
        bool v0 = g_vals[bat][warp * 64 + lane]      > MY_NEG_INF;
        bool v1 = g_vals[bat][warp * 64 + 32 + lane] > MY_NEG_INF;
        unsigned b0 = __ballot_sync(0xFFFFFFFFu, v0);
        unsigned b1 = __ballot_sync(0xFFFFFFFFu, v1);
        if (lane == 0) s_valid[warp] = (ull)b0 | ((ull)b1 << 32);
    }

    for (int i = tid; i < 2048; i += 1024) buf[0][i] = supp[i];
    __syncthreads();

    ull rem = 0ull;
    if (warp == 0) rem = ~s_valid[lane];

    for (int c = 0; c < 32; ++c) {
        if (warp == 0) {
            ull w64 = __shfl_sync(0xFFFFFFFFu, rem, c);
            const ull* bp = buf[c & 1];
#pragma unroll
            for (int bb = 0; bb < 64; ++bb) {
                ull srow = bp[bb * 32 + lane];
                ull sc   = bp[bb * 32 + c];
                ull msk  = ((w64 >> bb) & 1ull) - 1ull;
                rem |= srow & msk;
                w64 |= sc & msk;
            }
        } else if (c + 1 < 32) {
            for (int i = tid - 32; i < 2048; i += 992)
                buf[(c + 1) & 1][i] = supp[(size_t)(c + 1) * 2048 + i];
        }
        __syncthreads();
    }
    if (warp == 0) s_rem[lane] = rem;
    __syncthreads();

    const int SC_OFF = 0;
    const int BB_OFF = NB * NK;
    const int KP_OFF = NB * NK * 5;
    for (int k = tid; k < NK; k += 1024) {
        bool keep = ((s_rem[k >> 6] >> (k & 63)) & 1ull) == 0ull;
        float v = keep ? g_vals[bat][k] : 0.f;
        float4 bx = g_boxes[bat][k];
        if (!keep) bx = make_float4(0.f, 0.f, 0.f, 0.f);
        int gk = bat * NK + k;
        out[SC_OFF + gk] = v;
        float4* ob = (float4*)(out + BB_OFF);
        ob[gk] = bx;
        out[KP_OFF + gk] = keep ? 1.f : 0.f;
    }
}

// ---------------- launch ----------------
extern "C" void kernel_launch(void* const* d_in, const int* in_sizes, int n_in,
                              void* d_out, int out_size) {
    const float* scores = (const float*)d_in[0];
    const float* deltas = (const float*)d_in[1];
    const float* sizes  = (const float*)d_in[2];
    const int* p_stride = (const int*)d_in[3];
    const int* p_offy   = (const int*)d_in[4];
    const int* p_offx   = (const int*)d_in[5];
    float* out = (float*)d_out;

    cudaFuncSetAttribute(k_sort, cudaFuncAttributeMaxDynamicSharedMemorySize, 65536);

    k_peaks<<<dim3(NW / 128, NH / 8, NB), dim3(32, 8, 1)>>>(scores);
    k_thresh<<<NB, 1024>>>();
    k_compact<<<dim3(64, NB), 256>>>();
    k_sort<<<NB, 1024, 65536>>>(deltas, sizes, p_stride, p_offy, p_offx);
    k_iou<<<dim3(NK / 64, NK / 256, NB), 256>>>();
    k_final<<<NB, 1024>>>(out);
}

// round 17
// speedup vs baseline: 6.0273x; 1.3429x over previous
#include <cuda_runtime.h>
#include <cstdint>

// Problem constants (fixed shapes)
#define NB 8
#define NH 1024
#define NW 1024
#define NHW (1u << 20)
#define NK 2048
#define MY_NEG_INF (-1e30f)

typedef unsigned long long ull;

// ---------------- device scratch (static globals: no allocs allowed) ----------------
// Zero-initialized at module load; every kernel that consumes a counter/bitmap
// restores it to zero AFTER a __syncthreads() that orders all reads before the
// reset store (replay-determinism: graph replays must see identical state).
__device__ ull          g_cand[NB][NHW];      // packed (value_bits<<32)|~idx
__device__ int          g_cand_cnt[NB];
__device__ unsigned int g_hist[NB][4096];     // value histogram
__device__ unsigned int g_thrA[NB];           // lower bound of buckets > t
__device__ unsigned int g_thrB[NB];           // lower bound of boundary bucket t
__device__ ull          g_selA[NB][2048];     // strictly above boundary bucket
__device__ int          g_selA_cnt[NB];
__device__ ull          g_selB[NB][6144];     // boundary bucket
__device__ int          g_selB_cnt[NB];
__device__ ull          g_skey[NB][NK];       // sorted top-K keys
__device__ float        g_vals[NB][NK];
__device__ float4       g_boxes[NB][NK];      // x1,y1,x2,y2
__device__ ull          g_supp[NB][NK][32];   // suppression bitmask rows
__device__ ull          g_nzrow[NB][32];      // bitmap: rows with nonzero supp mask

// ---------------- K1: 3x3 local max + threshold, compact candidates ----------------
// block (32,8) = 256 thr, each thread does 4 px; tile 128x8; grid (8,128,NB)
__global__ void k_peaks(const float* __restrict__ scores) {
    __shared__ float s_t[10][136];
    const float NINF = __int_as_float(0xff800000);

    int bat = blockIdx.z;
    int tx = threadIdx.x, ty = threadIdx.y;
    int tid = ty * 32 + tx;
    const float* sb = scores + (size_t)bat * NHW;

    int bx0 = blockIdx.x * 128 - 4;
    int by0 = blockIdx.y * 8 - 1;

    for (int i = tid; i < 340; i += 256) {
        int r = i / 34, q = i - r * 34;
        int gy = by0 + r;
        int gx = bx0 + q * 4;
        float4 v = make_float4(NINF, NINF, NINF, NINF);
        if ((unsigned)gy < (unsigned)NH && (unsigned)gx < (unsigned)NW)
            v = *(const float4*)(sb + (size_t)gy * NW + gx);
        *(float4*)&s_t[r][q * 4] = v;
    }
    __syncthreads();

    int r = ty + 1;
    int c = 4 + 4 * tx;
    float4 L0 = *(const float4*)&s_t[r - 1][c - 4];
    float4 L1 = *(const float4*)&s_t[r    ][c - 4];
    float4 L2 = *(const float4*)&s_t[r + 1][c - 4];
    float4 M0 = *(const float4*)&s_t[r - 1][c];
    float4 M1 = *(const float4*)&s_t[r    ][c];
    float4 M2 = *(const float4*)&s_t[r + 1][c];
    float4 R0 = *(const float4*)&s_t[r - 1][c + 4];
    float4 R1 = *(const float4*)&s_t[r    ][c + 4];
    float4 R2 = *(const float4*)&s_t[r + 1][c + 4];

    float cm[6];
    cm[0] = fmaxf(fmaxf(L0.w, L1.w), L2.w);
    cm[1] = fmaxf(fmaxf(M0.x, M1.x), M2.x);
    cm[2] = fmaxf(fmaxf(M0.y, M1.y), M2.y);
    cm[3] = fmaxf(fmaxf(M0.z, M1.z), M2.z);
    cm[4] = fmaxf(fmaxf(M0.w, M1.w), M2.w);
    cm[5] = fmaxf(fmaxf(R0.x, R1.x), R2.x);

    float sv[4] = {M1.x, M1.y, M1.z, M1.w};
    bool cand[4];
#pragma unroll
    for (int j = 0; j < 4; ++j) {
        float m = fmaxf(fmaxf(cm[j], cm[j + 1]), cm[j + 2]);
        cand[j] = (sv[j] > 0.5f) && (sv[j] == m);
    }

    int gy = blockIdx.y * 8 + ty;
    int gx0 = blockIdx.x * 128 + 4 * tx;

    unsigned bal[4];
    int pc[4];
#pragma unroll
    for (int j = 0; j < 4; ++j) { bal[j] = __ballot_sync(0xFFFFFFFFu, cand[j]); pc[j] = __popc(bal[j]); }
    int tot = pc[0] + pc[1] + pc[2] + pc[3];
    if (tot) {
        int base = 0;
        if (tx == 0) base = atomicAdd(&g_cand_cnt[bat], tot);
        base = __shfl_sync(0xFFFFFFFFu, base, 0);
        unsigned lmask = (1u << tx) - 1u;
        int pre = 0;
#pragma unroll
        for (int j = 0; j < 4; ++j) {
            if (cand[j]) {
                int pos = base + pre + __popc(bal[j] & lmask);
                unsigned idx = (unsigned)(gy * NW + gx0 + j);
                unsigned vb = __float_as_uint(sv[j]);
                g_cand[bat][pos] = ((ull)vb << 32) | (unsigned)(~idx);
                int bkt = (int)(vb >> 11) - 0x7E000;
                bkt = bkt < 0 ? 0 : (bkt > 4095 ? 4095 : bkt);
                atomicAdd(&g_hist[bat][bkt], 1u);
            }
            pre += pc[j];
        }
    }
}

// ---------------- K2a: per-batch boundary bucket (warp-shuffle two-level scan) ----------------
// grid NB, block 1024
__global__ void k_thresh() {
    __shared__ unsigned s_wtot[32];
    __shared__ unsigned s_wsuf[33];
    __shared__ int s_tbkt;
    int bat = blockIdx.x;
    int tid = threadIdx.x;
    int warp = tid >> 5, lane = tid & 31;

    unsigned* hh = g_hist[bat];
    uint4 h = ((uint4*)hh)[tid];
    ((uint4*)hh)[tid] = make_uint4(0u, 0u, 0u, 0u);   // own bins only: race-free reset
    unsigned gsum = h.x + h.y + h.z + h.w;
    if (tid == 0) s_tbkt = 0;

    unsigned s = gsum;
#pragma unroll
    for (int d = 1; d < 32; d <<= 1) {
        unsigned o = __shfl_down_sync(0xFFFFFFFFu, s, d);
        if (lane + d < 32) s += o;
    }
    if (lane == 0) s_wtot[warp] = s;
    __syncthreads();
    if (warp == 0) {
        unsigned ts = s_wtot[lane];
#pragma unroll
        for (int d = 1; d < 32; d <<= 1) {
            unsigned o = __shfl_down_sync(0xFFFFFFFFu, ts, d);
            if (lane + d < 32) ts += o;
        }
        s_wsuf[lane] = ts;
        if (lane == 0) s_wsuf[32] = 0u;
    }
    __syncthreads();

    unsigned beyond = s_wsuf[warp + 1] + (s - gsum);
    unsigned S = beyond;
    int loc = -1;
    S += h.w; if (S >= NK) loc = 4 * tid + 3;
    if (loc < 0) { S += h.z; if (S >= NK) loc = 4 * tid + 2; }
    if (loc < 0) { S += h.y; if (S >= NK) loc = 4 * tid + 1; }
    if (loc < 0) { S += h.x; if (S >= NK) loc = 4 * tid + 0; }
    if (loc >= 0) atomicMax(&s_tbkt, loc);
    __syncthreads();
    if (tid == 0) {
        unsigned t = (unsigned)s_tbkt;
        g_thrB[bat] = (t + 0x7E000u) << 11;
        g_thrA[bat] = (t + 1u + 0x7E000u) << 11;
    }
}

// ---------------- K2b: compact survivors into A (above boundary) and B (boundary) ----------------
// grid (64, NB), block 256
__global__ void k_compact() {
    int bat = blockIdx.y;
    unsigned thrA = g_thrA[bat];
    unsigned thrB = g_thrB[bat];
    int n = g_cand_cnt[bat];
    int nv = (n + 1) >> 1;
    int step = gridDim.x * 256;
    int lane = threadIdx.x & 31;
    unsigned lmask = (1u << lane) - 1u;
    for (int i = blockIdx.x * 256 + threadIdx.x; i < nv; i += step) {
        ulonglong2 kk = *((const ulonglong2*)g_cand[bat] + i);
        unsigned v0 = (unsigned)(kk.x >> 32);
        unsigned v1 = (unsigned)(kk.y >> 32);
        bool in1 = (2 * i + 1 < n);
        bool a0 = v0 >= thrA;
        bool a1 = in1 && (v1 >= thrA);
        bool b0 = !a0 && (v0 >= thrB);
        bool b1 = in1 && !a1 && (v1 >= thrB);

        unsigned bA0 = __ballot_sync(0xFFFFFFFFu, a0);
        unsigned bA1 = __ballot_sync(0xFFFFFFFFu, a1);
        unsigned bB0 = __ballot_sync(0xFFFFFFFFu, b0);
        unsigned bB1 = __ballot_sync(0xFFFFFFFFu, b1);

        if (bA0 | bA1) {
            int t0 = __popc(bA0);
            int base = 0;
            if (lane == 0) base = atomicAdd(&g_selA_cnt[bat], t0 + __popc(bA1));
            base = __shfl_sync(0xFFFFFFFFu, base, 0);
            if (a0) { int p = base + __popc(bA0 & lmask); if (p < 2048) g_selA[bat][p] = kk.x; }
            if (a1) { int p = base + t0 + __popc(bA1 & lmask); if (p < 2048) g_selA[bat][p] = kk.y; }
        }
        if (bB0 | bB1) {
            int t0 = __popc(bB0);
            int base = 0;
            if (lane == 0) base = atomicAdd(&g_selB_cnt[bat], t0 + __popc(bB1));
            base = __shfl_sync(0xFFFFFFFFu, base, 0);
            if (b0) { int p = base + __popc(bB0 & lmask); if (p < 6144) g_selB[bat][p] = kk.x; }
            if (b1) { int p = base + t0 + __popc(bB1 & lmask); if (p < 6144) g_selB[bat][p] = kk.y; }
        }
    }
}

// ---------------- bitonic helpers ----------------
__device__ __forceinline__ void cex(ull& a, ull& b, bool desc) {
    bool sw = desc ? (a < b) : (a > b);
    ull t = sw ? b : a;
    b = sw ? a : b;
    a = t;
}

// ---------------- K2c: sort A (2048) + B (512) via reg/shfl bitonic, emit sorted keys ----------------
// 1 block (1024 thr) per batch; dynamic smem 64KB (fallback needs 8192 keys)
__global__ void k_sort() {
    extern __shared__ ull s_keys[];   // fast: [0..512)=B, [512..2560)=A ; fallback: [0..8192)
    int bat = blockIdx.x;
    int tid = threadIdx.x;

    int nA = g_selA_cnt[bat]; if (nA > 2048) nA = 2048;
    int nB = g_selB_cnt[bat]; if (nB > 6144) nB = 6144;
    // RACE FIX: all threads must finish reading the counters before the reset.
    __syncthreads();
    if (tid == 0) { g_selA_cnt[bat] = 0; g_selB_cnt[bat] = 0; g_cand_cnt[bat] = 0; }

    if (nB <= 512) {
        // ---- B: 512-element reg/shfl bitonic on threads 0..255 (2 elems/thread) ----
        ull* sB = s_keys;             // 512 slots
        int j0 = tid * 2;             // element index for B (tid < 256)
        ull b0 = 0ull, b1 = 0ull;
        if (tid < 256) {
            b0 = (j0     < nB) ? g_selB[bat][j0]     : 0ull;
            b1 = (j0 + 1 < nB) ? g_selB[bat][j0 + 1] : 0ull;
            cex(b0, b1, (j0 & 2) == 0);                 // k = 2
#pragma unroll
            for (int k = 4; k <= 64; k <<= 1) {         // barrier-free
                bool desc = ((j0 & k) == 0);
#pragma unroll
                for (int j = k >> 1; j >= 2; j >>= 1) {
                    unsigned lm = (unsigned)j >> 1;
                    bool keepmax = (((j0 & j) == 0) == desc);
                    ull o0 = __shfl_xor_sync(0xFFFFFFFFu, b0, lm);
                    b0 = keepmax ? (o0 > b0 ? o0 : b0) : (o0 < b0 ? o0 : b0);
                    ull o1 = __shfl_xor_sync(0xFFFFFFFFu, b1, lm);
                    b1 = keepmax ? (o1 > b1 ? o1 : b1) : (o1 < b1 ? o1 : b1);
                }
                cex(b0, b1, desc);
            }
        }
#pragma unroll 1
        for (int k = 128; k <= 512; k <<= 1) {
            if (tid < 256) { sB[j0] = b0; sB[j0 + 1] = b1; }
            __syncthreads();
#pragma unroll 1
            for (int j = k >> 1; j >= 64; j >>= 1) {
                if (tid < 256) {
                    int p = tid;
                    int i = ((p & ~(j - 1)) << 1) | (p & (j - 1));
                    int ixj = i | j;
                    ull x = sB[i];
                    ull y = sB[ixj];
                    bool sw = ((i & k) == 0) ? (x < y) : (x > y);
                    if (sw) { sB[i] = y; sB[ixj] = x; }
                }
                __syncthreads();
            }
            if (tid < 256) {
                b0 = sB[j0]; b1 = sB[j0 + 1];
                bool desc = ((j0 & k) == 0);
#pragma unroll
                for (int j = 32; j >= 2; j >>= 1) {
                    unsigned lm = (unsigned)j >> 1;
                    bool keepmax = (((j0 & j) == 0) == desc);
                    ull o0 = __shfl_xor_sync(0xFFFFFFFFu, b0, lm);
                    b0 = keepmax ? (o0 > b0 ? o0 : b0) : (o0 < b0 ? o0 : b0);
                    ull o1 = __shfl_xor_sync(0xFFFFFFFFu, b1, lm);
                    b1 = keepmax ? (o1 > b1 ? o1 : b1) : (o1 < b1 ? o1 : b1);
                }
                cex(b0, b1, desc);
            }
        }
        if (tid < 256) { sB[j0] = b0; sB[j0 + 1] = b1; }
        __syncthreads();

        // ---- A: 2048-element bitonic, 2 regs/thread ----
        ull* sA = s_keys + 512;
        int i0 = tid * 2;
        ull v0 = (i0     < nA) ? g_selA[bat][i0]     : 0ull;
        ull v1 = (i0 + 1 < nA) ? g_selA[bat][i0 + 1] : 0ull;

        cex(v0, v1, (i0 & 2) == 0);
#pragma unroll
        for (int k = 4; k <= 64; k <<= 1) {
            bool desc = ((i0 & k) == 0);
#pragma unroll
            for (int j = k >> 1; j >= 2; j >>= 1) {
                unsigned lm = (unsigned)j >> 1;
                bool keepmax = (((i0 & j) == 0) == desc);
                ull o0 = __shfl_xor_sync(0xFFFFFFFFu, v0, lm);
                v0 = keepmax ? (o0 > v0 ? o0 : v0) : (o0 < v0 ? o0 : v0);
                ull o1 = __shfl_xor_sync(0xFFFFFFFFu, v1, lm);
                v1 = keepmax ? (o1 > v1 ? o1 : v1) : (o1 < v1 ? o1 : v1);
            }
            cex(v0, v1, desc);
        }
#pragma unroll 1
        for (int k = 128; k <= 2048; k <<= 1) {
            sA[i0] = v0; sA[i0 + 1] = v1;
            __syncthreads();
#pragma unroll 1
            for (int j = k >> 1; j >= 64; j >>= 1) {
                int p = tid;
                int i = ((p & ~(j - 1)) << 1) | (p & (j - 1));
                int ixj = i | j;
                ull x = sA[i];
                ull y = sA[ixj];
                bool sw = ((i & k) == 0) ? (x < y) : (x > y);
                if (sw) { sA[i] = y; sA[ixj] = x; }
                __syncthreads();
            }
            v0 = sA[i0]; v1 = sA[i0 + 1];
            bool desc = ((i0 & k) == 0);
#pragma unroll
            for (int j = 32; j >= 2; j >>= 1) {
                unsigned lm = (unsigned)j >> 1;
                bool keepmax = (((i0 & j) == 0) == desc);
                ull o0 = __shfl_xor_sync(0xFFFFFFFFu, v0, lm);
                v0 = keepmax ? (o0 > v0 ? o0 : v0) : (o0 < v0 ? o0 : v0);
                ull o1 = __shfl_xor_sync(0xFFFFFFFFu, v1, lm);
                v1 = keepmax ? (o1 > v1 ? o1 : v1) : (o1 < v1 ? o1 : v1);
            }
            cex(v0, v1, desc);
        }

        // ---- top-2048 = sortedA[0..nA) ++ sortedB[0..2048-nA) ----
        {
            ull key0 = (i0 < nA) ? v0
                     : ((i0 - nA < nB) ? s_keys[i0 - nA] : 0ull);
            int k1 = i0 + 1;
            ull key1 = (k1 < nA) ? v1
                     : ((k1 - nA < nB) ? s_keys[k1 - nA] : 0ull);
            g_skey[bat][i0] = key0;
            g_skey[bat][k1] = key1;
        }
    } else {
        // ---- fallback: generic smem bitonic over A ++ B ----
        for (int i = tid; i < nA; i += 1024) s_keys[i] = g_selA[bat][i];
        for (int i = tid; i < nB; i += 1024) s_keys[nA + i] = g_selB[bat][i];
        int nsel = nA + nB;
        int nsort = NK;
        while (nsort < nsel) nsort <<= 1;
        for (int i = nsel + tid; i < nsort; i += 1024) s_keys[i] = 0ull;
        __syncthreads();
        int half = nsort >> 1;
        for (int k = 2; k <= nsort; k <<= 1) {
            for (int j = k >> 1; j > 0; j >>= 1) {
                for (int p = tid; p < half; p += 1024) {
                    int i = ((p & ~(j - 1)) << 1) | (p & (j - 1));
                    int ixj = i | j;
                    ull x = s_keys[i];
                    ull y = s_keys[ixj];
                    bool sw = ((i & k) == 0) ? (x < y) : (x > y);
                    if (sw) { s_keys[i] = y; s_keys[ixj] = x; }
                }
                __syncthreads();
            }
        }
        for (int k2 = tid; k2 < NK; k2 += 1024) g_skey[bat][k2] = s_keys[k2];
    }
}

// ---------------- K2d: decode sorted keys -> vals + boxes (full-chip) ----------------
// grid (8, NB), block 256
__global__ void k_decode(const float* __restrict__ deltas,
                         const float* __restrict__ sizes,
                         const int* __restrict__ p_stride,
                         const int* __restrict__ p_offy,
                         const int* __restrict__ p_offx) {
    int bat = blockIdx.y;
    int k2 = blockIdx.x * 256 + threadIdx.x;
    ull key = g_skey[bat][k2];
    int stride = p_stride[0];
    int offy   = p_offy[0];
    int offx   = p_offx[0];
    const float* dp = deltas + (size_t)bat * 2 * NHW;
    const float* sp = sizes  + (size_t)bat * 2 * NHW;

    float v;
    float4 box;
    if (key == 0ull) {
        v = MY_NEG_INF;
        box = make_float4(0.f, 0.f, 0.f, 0.f);
    } else {
        v = __uint_as_float((unsigned)(key >> 32));
        unsigned idx = ~(unsigned)key;
        int ih = (int)(idx >> 10);
        int iw = (int)(idx & 1023u);
        float dx = dp[idx];
        float dy = dp[NHW + idx];
        float sx = sp[idx];
        float sy = sp[NHW + idx];
        float cx = (float)(iw * stride + offx) + dx;
        float cy = (float)(ih * stride + offy) + dy;
        box = make_float4(cx - sx * 0.5f, cy - sy * 0.5f,
                          cx + sx * 0.5f, cy + sy * 0.5f);
    }
    g_vals[bat][k2]  = v;
    g_boxes[bat][k2] = box;
}

// ---------------- K3: suppression bitmask (256 rows x 64 cols per block) ----------------
// block 256 threads, grid (32, 8, NB)
__global__ void k_iou() {
    int bat = blockIdx.z, cb = blockIdx.x;
    int t = threadIdx.x;
    int row = blockIdx.y * 256 + t;
    int jbase = cb * 64;

    __shared__ float4 s_box[64];
    __shared__ float  s_area[64];
    if (t < 64) {
        float4 b = g_boxes[bat][jbase + t];
        s_box[t] = b;
        s_area[t] = (b.z - b.x) * (b.w - b.y);
    }
    __syncthreads();

    ull bits = 0ull;
    if (jbase + 63 > row) {
        float4 rbx = g_boxes[bat][row];
        float ra = (rbx.z - rbx.x) * (rbx.w - rbx.y);
        unsigned lo = 0u, hi = 0u;
        if (jbase > row) {
#pragma unroll
            for (int cc = 0; cc < 32; ++cc) {
                float4 o = s_box[cc];
                float iw = fminf(rbx.z, o.z) - fmaxf(rbx.x, o.x);
                float ih = fminf(rbx.w, o.w) - fmaxf(rbx.y, o.y);
                float inter = fmaxf(iw, 0.f) * fmaxf(ih, 0.f);
                unsigned sup = inter > 0.5f * (ra + s_area[cc] - inter + 1e-12f);
                lo |= sup << cc;
            }
#pragma unroll
            for (int cc = 32; cc < 64; ++cc) {
                float4 o = s_box[cc];
                float iw = fminf(rbx.z, o.z) - fmaxf(rbx.x, o.x);
                float ih = fminf(rbx.w, o.w) - fmaxf(rbx.y, o.y);
                float inter = fmaxf(iw, 0.f) * fmaxf(ih, 0.f);
                unsigned sup = inter > 0.5f * (ra + s_area[cc] - inter + 1e-12f);
                hi |= sup << (cc - 32);
            }
        } else {
#pragma unroll
            for (int cc = 0; cc < 32; ++cc) {
                float4 o = s_box[cc];
                float iw = fminf(rbx.z, o.z) - fmaxf(rbx.x, o.x);
                float ih = fminf(rbx.w, o.w) - fmaxf(rbx.y, o.y);
                float inter = fmaxf(iw, 0.f) * fmaxf(ih, 0.f);
                unsigned sup = (inter > 0.5f * (ra + s_area[cc] - inter + 1e-12f))
                               && (jbase + cc > row);
                lo |= sup << cc;
            }
#pragma unroll
            for (int cc = 32; cc < 64; ++cc) {
                float4 o = s_box[cc];
                float iw = fminf(rbx.z, o.z) - fmaxf(rbx.x, o.x);
                float ih = fminf(rbx.w, o.w) - fmaxf(rbx.y, o.y);
                float inter = fmaxf(iw, 0.f) * fmaxf(ih, 0.f);
                unsigned sup = (inter > 0.5f * (ra + s_area[cc] - inter + 1e-12f))
                               && (jbase + cc > row);
                hi |= sup << (cc - 32);
            }
        }
        bits = (ull)lo | ((ull)hi << 32);
    }
    g_supp[bat][row][cb] = bits;
    if (bits) atomicOr(&g_nzrow[bat][row >> 6], 1ull << (row & 63));
}

// ---------------- K4: sparse greedy reduction (only nonzero supp rows) + outputs ----------------
// 1 block (1024 thr) per batch
__global__ void k_final(float* __restrict__ out) {
    __shared__ ull s_data[144 * 32];           // 36KB: up to 144 rows' masks per pass
    __shared__ unsigned short s_rows[2048];    // 4KB: ordered nz row list
    __shared__ ull s_nz[32];
    __shared__ ull s_valid[32];
    __shared__ ull s_rem[32];
    __shared__ int s_tot;
    int bat = blockIdx.x;
    int tid = threadIdx.x;
    int warp = tid >> 5, lane = tid & 31;
    const ull* supp = &g_supp[bat][0][0];

    // valid bitmap (invalid rows start pre-removed)
    {
        bool v0 = g_vals[bat][warp * 64 + lane]      > MY_NEG_INF;
        bool v1 = g_vals[bat][warp * 64 + 32 + lane] > MY_NEG_INF;
        unsigned b0 = __ballot_sync(0xFFFFFFFFu, v0);
        unsigned b1 = __ballot_sync(0xFFFFFFFFu, v1);
        if (lane == 0) s_valid[warp] = (ull)b0 | ((ull)b1 << 32);
    }
    if (tid < 32) s_nz[tid] = g_nzrow[bat][tid];
    __syncthreads();
    // reset AFTER the barrier that orders all reads (replay determinism)
    if (tid < 32) g_nzrow[bat][tid] = 0ull;

    // build ordered row list (warp 0)
    if (warp == 0) {
        int cnt = __popcll(s_nz[lane]);
        int x = cnt;
#pragma unroll
        for (int d = 1; d < 32; d <<= 1) {
            int o = __shfl_up_sync(0xFFFFFFFFu, x, d);
            if (lane >= d) x += o;
        }
        int pre = x - cnt;
        if (lane == 31) s_tot = x;
        ull m = s_nz[lane];
        int p = pre;
        while (m) {
            int b = __ffsll(m) - 1;
            s_rows[p++] = (unsigned short)(lane * 64 + b);
            m &= m - 1;
        }
    }
    __syncthreads();
    int tot = s_tot;

    ull rem = 0ull;
    if (warp == 0) rem = ~s_valid[lane];   // lane owns removed-word 'lane'

    for (int base = 0; base < tot; base += 144) {
        int m = tot - base; if (m > 144) m = 144;
        // gather nz rows' full masks into smem (coalesced)
        for (int e = tid; e < m * 32; e += 1024) {
            int idx = e >> 5, w = e & 31;
            s_data[e] = supp[(size_t)s_rows[base + idx] * 32 + w];
        }
        __syncthreads();
        if (warp == 0) {
            for (int idx = 0; idx < m; ++idx) {
                int r = s_rows[base + idx];
                ull wv = __shfl_sync(0xFFFFFFFFu, rem, r >> 6);
                if (!((wv >> (r & 63)) & 1ull))
                    rem |= s_data[idx * 32 + lane];
            }
        }
        __syncthreads();
    }
    if (warp == 0) s_rem[lane] = rem;
    __syncthreads();

    // outputs: [scores (B*K)] [bboxes (B*K*4)] [keep (B*K)] as fp32
    const int SC_OFF = 0;
    const int BB_OFF = NB * NK;
    const int KP_OFF = NB * NK * 5;
    for (int k = tid; k < NK; k += 1024) {
        bool keep = ((s_rem[k >> 6] >> (k & 63)) & 1ull) == 0ull;
        float v = keep ? g_vals[bat][k] : 0.f;
        float4 bx = g_boxes[bat][k];
        if (!keep) bx = make_float4(0.f, 0.f, 0.f, 0.f);
        int gk = bat * NK + k;
        out[SC_OFF + gk] = v;
        float4* ob = (float4*)(out + BB_OFF);
        ob[gk] = bx;
        out[KP_OFF + gk] = keep ? 1.f : 0.f;
    }
}

// ---------------- launch ----------------
extern "C" void kernel_launch(void* const* d_in, const int* in_sizes, int n_in,
                              void* d_out, int out_size) {
    const float* scores = (const float*)d_in[0];
    const float* deltas = (const float*)d_in[1];
    const float* sizes  = (const float*)d_in[2];
    const int* p_stride = (const int*)d_in[3];
    const int* p_offy   = (const int*)d_in[4];
    const int* p_offx   = (const int*)d_in[5];
    float* out = (float*)d_out;

    cudaFuncSetAttribute(k_sort, cudaFuncAttributeMaxDynamicSharedMemorySize, 65536);

    k_peaks<<<dim3(NW / 128, NH / 8, NB), dim3(32, 8, 1)>>>(scores);
    k_thresh<<<NB, 1024>>>();
    k_compact<<<dim3(64, NB), 256>>>();
    k_sort<<<NB, 1024, 65536>>>();
    k_decode<<<dim3(NK / 256, NB), 256>>>(deltas, sizes, p_stride, p_offy, p_offx);
    k_iou<<<dim3(NK / 64, NK / 256, NB), 256>>>();
    k_final<<<NB, 1024>>>(out);
}